// round 13
// baseline (speedup 1.0000x reference)
#include <cuda_runtime.h>
#include <cuda_bf16.h>
#include <math.h>
#include <stdint.h>

// Problem constants: B=1, N=4096, E=256, H=8, D=32
#define N_TOK 4096
#define E_DIM 256
#define H_NUM 8
#define D_HEAD 32
#define SROW 40          // bf16 elems per smem row (80 B: conflict-free ldmatrix)
#define XPAIRS (N_TOK * E_DIM / 2)
#define WPAIRS (E_DIM * E_DIM / 2)
#define NSPLIT 2

typedef unsigned int u32;

// Scratch (device globals; no allocation allowed)
__device__ __nv_bfloat16 g_xh[N_TOK * E_DIM], g_xl[N_TOK * E_DIM];   // split x
__device__ __nv_bfloat16 g_wh[4][E_DIM * E_DIM], g_wl[4][E_DIM * E_DIM]; // Wq,Wk,Wv,Wo
__device__ __nv_bfloat16 g_qh[N_TOK * E_DIM], g_ql[N_TOK * E_DIM];
__device__ __nv_bfloat16 g_kh[N_TOK * E_DIM], g_kl[N_TOK * E_DIM];
__device__ __nv_bfloat16 g_vh[N_TOK * E_DIM], g_vl[N_TOK * E_DIM];
__device__ __nv_bfloat16 g_ah[N_TOK * E_DIM], g_al[N_TOK * E_DIM];   // attn out (split)
// Bitmask: g_adjT[cw * N_TOK + r], bit j = adjacency[r][cw*32+j] != 0
__device__ unsigned g_adjT[(N_TOK / 32) * N_TOK];
// Split-K partials (max-free: only unnormalized O and l needed)
__device__ float g_po[NSPLIT][H_NUM * N_TOK * D_HEAD];   // 2 x 16 MB
__device__ float g_pl[NSPLIT][H_NUM * N_TOK];

// ---------------------------------------------------------------------------
// MMA / ldmatrix / cp.async helpers
// ---------------------------------------------------------------------------
__device__ __forceinline__ u32 cvta_s(const void* p) {
    return (u32)__cvta_generic_to_shared(p);
}
__device__ __forceinline__ void ldsm_x4(u32* r, u32 a) {
    asm volatile("ldmatrix.sync.aligned.m8n8.x4.shared.b16 {%0,%1,%2,%3}, [%4];"
        : "=r"(r[0]), "=r"(r[1]), "=r"(r[2]), "=r"(r[3]) : "r"(a));
}
__device__ __forceinline__ void ldsm_x4t(u32* r, u32 a) {
    asm volatile("ldmatrix.sync.aligned.m8n8.x4.trans.shared.b16 {%0,%1,%2,%3}, [%4];"
        : "=r"(r[0]), "=r"(r[1]), "=r"(r[2]), "=r"(r[3]) : "r"(a));
}
__device__ __forceinline__ void ldsm_x2(u32* r, u32 a) {
    asm volatile("ldmatrix.sync.aligned.m8n8.x2.shared.b16 {%0,%1}, [%2];"
        : "=r"(r[0]), "=r"(r[1]) : "r"(a));
}
__device__ __forceinline__ void mma_bf16(float* c, const u32* a, const u32* b) {
    asm volatile("mma.sync.aligned.m16n8k16.row.col.f32.bf16.bf16.f32 "
        "{%0,%1,%2,%3}, {%4,%5,%6,%7}, {%8,%9}, {%0,%1,%2,%3};"
        : "+f"(c[0]), "+f"(c[1]), "+f"(c[2]), "+f"(c[3])
        : "r"(a[0]), "r"(a[1]), "r"(a[2]), "r"(a[3]), "r"(b[0]), "r"(b[1]));
}
__device__ __forceinline__ void cpasync16(u32 dst, const void* src) {
    asm volatile("cp.async.ca.shared.global [%0], [%1], 16;" :: "r"(dst), "l"(src));
}
__device__ __forceinline__ void cp_commit() {
    asm volatile("cp.async.commit_group;");
}
template <int N>
__device__ __forceinline__ void cp_wait() {
    asm volatile("cp.async.wait_group %0;" :: "n"(N));
}
// pack2(f_low, f_high): bf16x2 reg, low half = first element
__device__ __forceinline__ u32 pack2(float flo, float fhi) {
    u32 d;
    asm("cvt.rn.bf16x2.f32 %0, %1, %2;" : "=r"(d) : "f"(fhi), "f"(flo));
    return d;
}
// Dekker split of a pair into hi bf16x2 + lo bf16x2 (residual)
__device__ __forceinline__ void split_pair(float f0, float f1, u32& hi, u32& lo) {
    u32 h = pack2(f0, f1);
    float h0 = __uint_as_float(h << 16);
    float h1 = __uint_as_float(h & 0xffff0000u);
    lo = pack2(f0 - h0, f1 - h1);
    hi = h;
}

// ---------------------------------------------------------------------------
// Kernel 0: split fp32 inputs (x and the 4 weight matrices) into bf16 hi/lo.
// ---------------------------------------------------------------------------
__global__ void split_inputs(const float* __restrict__ x,
                             const float* __restrict__ Wq, const float* __restrict__ Wk,
                             const float* __restrict__ Wv, const float* __restrict__ Wo) {
    int i = blockIdx.x * 256 + threadIdx.x;
    const float* src;
    __nv_bfloat16 *dh, *dl;
    int off;
    if (i < XPAIRS) {
        src = x; dh = g_xh; dl = g_xl; off = i;
    } else {
        int j = i - XPAIRS;
        int w = j / WPAIRS;
        off = j - w * WPAIRS;
        src = (w == 0) ? Wq : (w == 1) ? Wk : (w == 2) ? Wv : Wo;
        dh = g_wh[w]; dl = g_wl[w];
    }
    float2 v = ((const float2*)src)[off];
    u32 h, l;
    split_pair(v.x, v.y, h, l);
    ((u32*)dh)[off] = h;
    ((u32*)dl)[off] = l;
}

// ---------------------------------------------------------------------------
// Kernel 1: pack adjacency (int32 0/1) into transposed bitmask.
// ---------------------------------------------------------------------------
__global__ void pack_adj_kernel(const int* __restrict__ adj) {
    int gw = (blockIdx.x * blockDim.x + threadIdx.x) >> 5;
    int lane = threadIdx.x & 31;
    int r  = gw >> 7;
    int cw = gw & 127;
    int v = adj[(size_t)r * N_TOK + cw * 32 + lane];
    unsigned b = __ballot_sync(0xffffffffu, v != 0);
    if (lane == 0) g_adjT[(size_t)cw * N_TOK + r] = b;
}

// ---------------------------------------------------------------------------
// MMA GEMM mainloop: C[128x64] tile of A[4096,256] @ B[64,256]^T, 3-term bf16.
// ---------------------------------------------------------------------------
#define PROJ_MAINLOOP(Ah, Al, Bh, Bl, mt, nt)                                   \
    __shared__ __align__(16) __nv_bfloat16 sAh[128 * SROW], sAl[128 * SROW];    \
    __shared__ __align__(16) __nv_bfloat16 sBh[64 * SROW],  sBl[64 * SROW];     \
    const int tid = threadIdx.x;                                                \
    const int lane = tid & 31;                                                  \
    const int wp = tid >> 5;                                                    \
    float c[8][4];                                                              \
    _Pragma("unroll")                                                           \
    for (int ng = 0; ng < 8; ng++)                                              \
        c[ng][0] = c[ng][1] = c[ng][2] = c[ng][3] = 0.f;                        \
    const int ar0 = tid >> 2,         ad = tid & 3;                             \
    const int ar1 = (tid + 256) >> 2;                                           \
    const int br  = tid >> 2,         bd = tid & 3;                             \
    const u32 dAh = cvta_s(sAh), dAl = cvta_s(sAl);                             \
    const u32 dBh = cvta_s(sBh), dBl = cvta_s(sBl);                             \
    for (int kc = 0; kc < 8; kc++) {                                            \
        const int k0 = kc * 32;                                                 \
        __syncthreads();                                                        \
        cpasync16(dAh + ar0 * 80 + ad * 16,                                     \
                  Ah + (size_t)(mt * 128 + ar0) * E_DIM + k0 + ad * 8);         \
        cpasync16(dAh + ar1 * 80 + ad * 16,                                     \
                  Ah + (size_t)(mt * 128 + ar1) * E_DIM + k0 + ad * 8);         \
        cpasync16(dAl + ar0 * 80 + ad * 16,                                     \
                  Al + (size_t)(mt * 128 + ar0) * E_DIM + k0 + ad * 8);         \
        cpasync16(dAl + ar1 * 80 + ad * 16,                                     \
                  Al + (size_t)(mt * 128 + ar1) * E_DIM + k0 + ad * 8);         \
        cpasync16(dBh + br * 80 + bd * 16,                                      \
                  Bh + (size_t)(nt * 64 + br) * E_DIM + k0 + bd * 8);           \
        cpasync16(dBl + br * 80 + bd * 16,                                      \
                  Bl + (size_t)(nt * 64 + br) * E_DIM + k0 + bd * 8);           \
        cp_commit();                                                            \
        cp_wait<0>();                                                           \
        __syncthreads();                                                        \
        _Pragma("unroll")                                                       \
        for (int ks = 0; ks < 2; ks++) {                                        \
            u32 ah[4], al[4];                                                   \
            u32 ao = (wp * 16 + (lane & 15)) * 80 + ks * 32 + (lane >> 4) * 16; \
            ldsm_x4(ah, dAh + ao);                                              \
            ldsm_x4(al, dAl + ao);                                              \
            const u32 kof = (lane & 7) * 80 + ((lane >> 3) & 1) * 16 + ks * 32; \
            _Pragma("unroll")                                                   \
            for (int ng = 0; ng < 8; ng++) {                                    \
                u32 bh[2], bl[2];                                               \
                ldsm_x2(bh, dBh + kof + ng * 640);                              \
                ldsm_x2(bl, dBl + kof + ng * 640);                              \
                mma_bf16(c[ng], ah, bh);                                        \
                mma_bf16(c[ng], ah, bl);                                        \
                mma_bf16(c[ng], al, bh);                                        \
            }                                                                   \
        }                                                                       \
    }

// Q/K/V projections via MMA, grid (4, 32, 3): nt, mt, which.
__global__ void __launch_bounds__(256) proj_mma(const float* __restrict__ bq,
                                                const float* __restrict__ bk,
                                                const float* __restrict__ bv) {
    const int nt = blockIdx.x, mt = blockIdx.y, which = blockIdx.z;
    const __nv_bfloat16* Ah = g_xh;
    const __nv_bfloat16* Al = g_xl;
    const __nv_bfloat16* Bh = g_wh[which];
    const __nv_bfloat16* Bl = g_wl[which];
    const float* bias = (which == 0) ? bq : (which == 1) ? bk : bv;
    const float scale = (which == 0)
        ? 0.17677669529663688f * 1.4426950408889634f   // 1/sqrt(32) * log2(e)
        : 1.0f;
    __nv_bfloat16* Ch = (which == 0) ? g_qh : (which == 1) ? g_kh : g_vh;
    __nv_bfloat16* Cl = (which == 0) ? g_ql : (which == 1) ? g_kl : g_vl;

    PROJ_MAINLOOP(Ah, Al, Bh, Bl, mt, nt)

    const int r0 = mt * 128 + wp * 16 + (lane >> 2);
    const int r1 = r0 + 8;
#pragma unroll
    for (int ng = 0; ng < 8; ng++) {
        int col = nt * 64 + ng * 8 + 2 * (lane & 3);
        float b0 = bias[col], b1 = bias[col + 1];
        float v0 = (c[ng][0] + b0) * scale;
        float v1 = (c[ng][1] + b1) * scale;
        float v2 = (c[ng][2] + b0) * scale;
        float v3 = (c[ng][3] + b1) * scale;
        u32 h, l;
        split_pair(v0, v1, h, l);
        *(u32*)(Ch + (size_t)r0 * E_DIM + col) = h;
        *(u32*)(Cl + (size_t)r0 * E_DIM + col) = l;
        split_pair(v2, v3, h, l);
        *(u32*)(Ch + (size_t)r1 * E_DIM + col) = h;
        *(u32*)(Cl + (size_t)r1 * E_DIM + col) = l;
    }
}

// Output projection via MMA, grid (4, 32). A = attention output (pre-split).
__global__ void __launch_bounds__(256) out_mma(const float* __restrict__ bo,
                                               float* __restrict__ out) {
    const int nt = blockIdx.x, mt = blockIdx.y;

    PROJ_MAINLOOP(g_ah, g_al, g_wh[3], g_wl[3], mt, nt)

    const int r0 = mt * 128 + wp * 16 + (lane >> 2);
    const int r1 = r0 + 8;
#pragma unroll
    for (int ng = 0; ng < 8; ng++) {
        int col = nt * 64 + ng * 8 + 2 * (lane & 3);
        float b0 = bo[col], b1 = bo[col + 1];
        float2 s0 = make_float2(c[ng][0] + b0, c[ng][1] + b1);
        float2 s1 = make_float2(c[ng][2] + b0, c[ng][3] + b1);
        *(float2*)(out + (size_t)r0 * E_DIM + col) = s0;
        *(float2*)(out + (size_t)r1 * E_DIM + col) = s1;
    }
}

// ---------------------------------------------------------------------------
// Kernel 3: split-K(x2) tensor-core masked flash attention, max-free exp2
// softmax, cp.async double buffer, x4 ldmatrix. Grid (32, 8, 2), 256 threads
// (8 warps). Block: 128 query rows; warp: 16 rows; key tiles of 64. The K/V
// smem double buffer is amortized over 2x the warps of round 12.
// ---------------------------------------------------------------------------
__global__ void __launch_bounds__(256) attn_mma_kernel() {
    __shared__ __align__(16) __nv_bfloat16 sKh[2][64 * SROW], sKl[2][64 * SROW];
    __shared__ __align__(16) __nv_bfloat16 sVh[2][64 * SROW], sVl[2][64 * SROW];

    const int tid = threadIdx.x;
    const int lane = tid & 31;
    const int wp = tid >> 5;           // 0..7
    const int h = blockIdx.y;
    const int z = blockIdx.z;
    const int qb = blockIdx.x * 128;
    const int jt0 = z * 32;            // this split's key-tile range

    // K/V staging: 64 rows x 4 chunks = 256 chunks of 16B; 1 per thread.
    const int srow = tid >> 2, sdp = tid & 3;
    const int so = srow * 80 + sdp * 16;

    // ---- Stage Q tile (128 rows, hi/lo) into the flattened K double buffer --
    {
#pragma unroll
        for (int i = 0; i < 2; i++) {
            int c = tid + i * 256;            // 0..511
            int row = c >> 2, dp = c & 3;     // 128 rows x 4 chunks
            size_t g = (size_t)(qb + row) * E_DIM + h * D_HEAD + dp * 8;
            int qo = row * 80 + dp * 16;      // spans both stages (10 KB)
            *(uint4*)((char*)sKh + qo) = *(const uint4*)(g_qh + g);
            *(uint4*)((char*)sKl + qo) = *(const uint4*)(g_ql + g);
        }
    }
    __syncthreads();

    u32 qh[2][4], ql[2][4];
    {
        int arow = wp * 16 + (lane & 15);     // 0..127
        int acol = (lane >> 4) * 8;
        u32 bh = cvta_s(sKh), bl = cvta_s(sKl);
#pragma unroll
        for (int ks = 0; ks < 2; ks++) {
            u32 ao = arow * 80 + (ks * 16 + acol) * 2;
            ldsm_x4(qh[ks], bh + ao);
            ldsm_x4(ql[ks], bl + ao);
        }
    }
    __syncthreads();

    // ---- Prefetch this split's first key tile into stage 0 ----
    {
        size_t g = (size_t)(jt0 * 64 + srow) * E_DIM + h * D_HEAD + sdp * 8;
        cpasync16(cvta_s(sKh[0]) + so, g_kh + g);
        cpasync16(cvta_s(sKl[0]) + so, g_kl + g);
        cpasync16(cvta_s(sVh[0]) + so, g_vh + g);
        cpasync16(cvta_s(sVl[0]) + so, g_vl + g);
        cp_commit();
    }

    float o[4][4];
#pragma unroll
    for (int nd = 0; nd < 4; nd++)
        o[nd][0] = o[nd][1] = o[nd][2] = o[nd][3] = 0.f;
    float l0 = 0.f, l1 = 0.f;

    const int r0 = qb + wp * 16 + (lane >> 2);
    const int r1 = r0 + 8;

    const u32 kofs4 = (((lane >> 4) & 1) * 8 + (lane & 7)) * 80
                    + ((lane >> 3) & 1) * 16;
    const u32 vofs4 = (lane & 15) * 80 + ((lane >> 4) & 1) * 16;

    for (int jj = 0; jj < 32; jj++) {
        const int jt = jt0 + jj;
        const int cur = jj & 1, nxt = cur ^ 1;

        if (jj + 1 < 32) {
            size_t g = (size_t)((jt + 1) * 64 + srow) * E_DIM + h * D_HEAD + sdp * 8;
            cpasync16(cvta_s(sKh[nxt]) + so, g_kh + g);
            cpasync16(cvta_s(sKl[nxt]) + so, g_kl + g);
            cpasync16(cvta_s(sVh[nxt]) + so, g_vh + g);
            cpasync16(cvta_s(sVl[nxt]) + so, g_vl + g);
            cp_commit();
            cp_wait<1>();
        } else {
            cp_wait<0>();
        }

        u32 w00 = g_adjT[(size_t)(jt * 2 + 0) * N_TOK + r0];
        u32 w01 = g_adjT[(size_t)(jt * 2 + 1) * N_TOK + r0];
        u32 w10 = g_adjT[(size_t)(jt * 2 + 0) * N_TOK + r1];
        u32 w11 = g_adjT[(size_t)(jt * 2 + 1) * N_TOK + r1];
        __syncthreads();

        const u32 kaH = cvta_s(sKh[cur]) + kofs4, kaL = cvta_s(sKl[cur]) + kofs4;
        const u32 vaH = cvta_s(sVh[cur]) + vofs4, vaL = cvta_s(sVl[cur]) + vofs4;

        // ---- S = Q @ K^T (4 n-frag pairs via x4, 2 k-steps, 3-term) ----
        float s[8][4];
#pragma unroll
        for (int np = 0; np < 4; np++) {
            s[2 * np][0] = s[2 * np][1] = s[2 * np][2] = s[2 * np][3] = 0.f;
            s[2 * np + 1][0] = s[2 * np + 1][1] = 0.f;
            s[2 * np + 1][2] = s[2 * np + 1][3] = 0.f;
#pragma unroll
            for (int ks = 0; ks < 2; ks++) {
                u32 bh[4], bl[4];
                u32 off = np * 1280 + ks * 32;
                ldsm_x4(bh, kaH + off);
                ldsm_x4(bl, kaL + off);
                mma_bf16(s[2 * np], qh[ks], bh);
                mma_bf16(s[2 * np], qh[ks], bl);
                mma_bf16(s[2 * np], ql[ks], bh);
                mma_bf16(s[2 * np + 1], qh[ks], bh + 2);
                mma_bf16(s[2 * np + 1], qh[ks], bl + 2);
                mma_bf16(s[2 * np + 1], ql[ks], bh + 2);
            }
        }

        // ---- mask + MAX-FREE softmax: p = exp2(s) ----
        const int sh2 = 2 * (lane & 3);
#pragma unroll
        for (int ng = 0; ng < 8; ng++) {
            u32 wr0 = (ng < 4) ? w00 : w01;
            u32 wr1 = (ng < 4) ? w10 : w11;
            int sh = (ng & 3) * 8 + sh2;
            if (!((wr0 >> sh) & 1))       s[ng][0] = -INFINITY;
            if (!((wr0 >> (sh + 1)) & 1)) s[ng][1] = -INFINITY;
            if (!((wr1 >> sh) & 1))       s[ng][2] = -INFINITY;
            if (!((wr1 >> (sh + 1)) & 1)) s[ng][3] = -INFINITY;
        }
#pragma unroll
        for (int ng = 0; ng < 8; ng++) {
            s[ng][0] = exp2f(s[ng][0]);
            s[ng][1] = exp2f(s[ng][1]);
            s[ng][2] = exp2f(s[ng][2]);
            s[ng][3] = exp2f(s[ng][3]);
            l0 += s[ng][0] + s[ng][1];
            l1 += s[ng][2] + s[ng][3];
        }

        // ---- O += P @ V (4 key-steps, dim-frag pairs via x4 trans) ----
#pragma unroll
        for (int ks = 0; ks < 4; ks++) {
            u32 ah[4], alo[4];
            split_pair(s[2 * ks][0],     s[2 * ks][1],     ah[0], alo[0]);
            split_pair(s[2 * ks][2],     s[2 * ks][3],     ah[1], alo[1]);
            split_pair(s[2 * ks + 1][0], s[2 * ks + 1][1], ah[2], alo[2]);
            split_pair(s[2 * ks + 1][2], s[2 * ks + 1][3], ah[3], alo[3]);
#pragma unroll
            for (int np = 0; np < 2; np++) {
                u32 bh[4], bl[4];
                u32 off = ks * 1280 + np * 32;
                ldsm_x4t(bh, vaH + off);
                ldsm_x4t(bl, vaL + off);
                mma_bf16(o[2 * np], ah, bh);
                mma_bf16(o[2 * np], ah, bl);
                mma_bf16(o[2 * np], alo, bh);
                mma_bf16(o[2 * np + 1], ah, bh + 2);
                mma_bf16(o[2 * np + 1], ah, bl + 2);
                mma_bf16(o[2 * np + 1], alo, bh + 2);
            }
        }
        __syncthreads();
    }

    // ---- write unnormalized partials (max-free: no m, no alpha) ----
    l0 += __shfl_xor_sync(0xffffffffu, l0, 1);
    l0 += __shfl_xor_sync(0xffffffffu, l0, 2);
    l1 += __shfl_xor_sync(0xffffffffu, l1, 1);
    l1 += __shfl_xor_sync(0xffffffffu, l1, 2);
    const int idx0 = h * N_TOK + r0;
    const int idx1 = h * N_TOK + r1;
    if ((lane & 3) == 0) {
        g_pl[z][idx0] = l0;
        g_pl[z][idx1] = l1;
    }
    float* p0 = &g_po[z][(size_t)idx0 * D_HEAD];
    float* p1 = &g_po[z][(size_t)idx1 * D_HEAD];
#pragma unroll
    for (int nd = 0; nd < 4; nd++) {
        int cn = nd * 8 + 2 * (lane & 3);
        *(float2*)(p0 + cn) = make_float2(o[nd][0], o[nd][1]);
        *(float2*)(p1 + cn) = make_float2(o[nd][2], o[nd][3]);
    }
}

// ---------------------------------------------------------------------------
// Kernel 4: combine the 2 split partials, normalize, write hi/lo bf16 split.
// One thread per (h,row,4-dim chunk): H*N*8 = 262144 threads.
// ---------------------------------------------------------------------------
__global__ void combine_kernel() {
    int c = blockIdx.x * 256 + threadIdx.x;
    int cc = c & 7;
    int idx = c >> 3;                 // h*N + r
    float inv = 1.f / (g_pl[0][idx] + g_pl[1][idx]);
    float4 a = *(const float4*)&g_po[0][(size_t)idx * D_HEAD + cc * 4];
    float4 b = *(const float4*)&g_po[1][(size_t)idx * D_HEAD + cc * 4];
    float v0 = (a.x + b.x) * inv;
    float v1 = (a.y + b.y) * inv;
    float v2 = (a.z + b.z) * inv;
    float v3 = (a.w + b.w) * inv;
    int r = idx & (N_TOK - 1);
    int h = idx >> 12;
    size_t off = (size_t)r * E_DIM + h * D_HEAD + cc * 4;
    u32 hh, ll;
    split_pair(v0, v1, hh, ll);
    *(u32*)(g_ah + off) = hh;
    *(u32*)(g_al + off) = ll;
    split_pair(v2, v3, hh, ll);
    *(u32*)(g_ah + off + 2) = hh;
    *(u32*)(g_al + off + 2) = ll;
}

// ---------------------------------------------------------------------------
extern "C" void kernel_launch(void* const* d_in, const int* in_sizes, int n_in,
                              void* d_out, int out_size) {
    const float* x   = (const float*)d_in[0];
    const int*   adj = (const int*)d_in[1];
    const float* Wq  = (const float*)d_in[2];
    const float* bq  = (const float*)d_in[3];
    const float* Wk  = (const float*)d_in[4];
    const float* bk  = (const float*)d_in[5];
    const float* Wv  = (const float*)d_in[6];
    const float* bv  = (const float*)d_in[7];
    const float* Wo  = (const float*)d_in[8];
    const float* bo  = (const float*)d_in[9];
    float* out = (float*)d_out;

    split_inputs<<<(XPAIRS + 4 * WPAIRS) / 256, 256>>>(x, Wq, Wk, Wv, Wo);

    pack_adj_kernel<<<(N_TOK * 128) / 8, 256>>>(adj);

    proj_mma<<<dim3(4, 32, 3), 256>>>(bq, bk, bv);

    attn_mma_kernel<<<dim3(N_TOK / 128, H_NUM, NSPLIT), 256>>>();

    combine_kernel<<<(H_NUM * N_TOK * 8) / 256, 256>>>();

    out_mma<<<dim3(4, 32), 256>>>(bo, out);
}

// round 14
// speedup vs baseline: 1.0487x; 1.0487x over previous
#include <cuda_runtime.h>
#include <cuda_bf16.h>
#include <math.h>
#include <stdint.h>

// Problem constants: B=1, N=4096, E=256, H=8, D=32
#define N_TOK 4096
#define E_DIM 256
#define H_NUM 8
#define D_HEAD 32
#define SROW 40          // bf16 elems per smem row (80 B: conflict-free ldmatrix)
#define XPAIRS (N_TOK * E_DIM / 2)
#define WPAIRS (E_DIM * E_DIM / 2)
#define NSPLIT 4
#define TILES_PER_SPLIT (64 / NSPLIT)   // 16 key-tiles of 64 keys

typedef unsigned int u32;

// Scratch (device globals; no allocation allowed)
__device__ __nv_bfloat16 g_xh[N_TOK * E_DIM], g_xl[N_TOK * E_DIM];   // split x
__device__ __nv_bfloat16 g_wh[4][E_DIM * E_DIM], g_wl[4][E_DIM * E_DIM]; // Wq,Wk,Wv,Wo
__device__ __nv_bfloat16 g_qh[N_TOK * E_DIM], g_ql[N_TOK * E_DIM];
__device__ __nv_bfloat16 g_kh[N_TOK * E_DIM], g_kl[N_TOK * E_DIM];
__device__ __nv_bfloat16 g_vh[N_TOK * E_DIM], g_vl[N_TOK * E_DIM];
__device__ __nv_bfloat16 g_ah[N_TOK * E_DIM], g_al[N_TOK * E_DIM];   // attn out (split)
// Bitmask: g_adjT[cw * N_TOK + r], bit j = adjacency[r][cw*32+j] != 0
__device__ unsigned g_adjT[(N_TOK / 32) * N_TOK];
// Split-K partials (max-free: only unnormalized O and l needed); 4 MB per split
__device__ float g_po[NSPLIT][H_NUM * N_TOK * D_HEAD];
__device__ float g_pl[NSPLIT][H_NUM * N_TOK];

// ---------------------------------------------------------------------------
// MMA / ldmatrix / cp.async helpers
// ---------------------------------------------------------------------------
__device__ __forceinline__ u32 cvta_s(const void* p) {
    return (u32)__cvta_generic_to_shared(p);
}
__device__ __forceinline__ void ldsm_x4(u32* r, u32 a) {
    asm volatile("ldmatrix.sync.aligned.m8n8.x4.shared.b16 {%0,%1,%2,%3}, [%4];"
        : "=r"(r[0]), "=r"(r[1]), "=r"(r[2]), "=r"(r[3]) : "r"(a));
}
__device__ __forceinline__ void ldsm_x4t(u32* r, u32 a) {
    asm volatile("ldmatrix.sync.aligned.m8n8.x4.trans.shared.b16 {%0,%1,%2,%3}, [%4];"
        : "=r"(r[0]), "=r"(r[1]), "=r"(r[2]), "=r"(r[3]) : "r"(a));
}
__device__ __forceinline__ void ldsm_x2(u32* r, u32 a) {
    asm volatile("ldmatrix.sync.aligned.m8n8.x2.shared.b16 {%0,%1}, [%2];"
        : "=r"(r[0]), "=r"(r[1]) : "r"(a));
}
__device__ __forceinline__ void mma_bf16(float* c, const u32* a, const u32* b) {
    asm volatile("mma.sync.aligned.m16n8k16.row.col.f32.bf16.bf16.f32 "
        "{%0,%1,%2,%3}, {%4,%5,%6,%7}, {%8,%9}, {%0,%1,%2,%3};"
        : "+f"(c[0]), "+f"(c[1]), "+f"(c[2]), "+f"(c[3])
        : "r"(a[0]), "r"(a[1]), "r"(a[2]), "r"(a[3]), "r"(b[0]), "r"(b[1]));
}
__device__ __forceinline__ void cpasync16(u32 dst, const void* src) {
    asm volatile("cp.async.ca.shared.global [%0], [%1], 16;" :: "r"(dst), "l"(src));
}
__device__ __forceinline__ void cp_commit() {
    asm volatile("cp.async.commit_group;");
}
template <int N>
__device__ __forceinline__ void cp_wait() {
    asm volatile("cp.async.wait_group %0;" :: "n"(N));
}
// pack2(f_low, f_high): bf16x2 reg, low half = first element
__device__ __forceinline__ u32 pack2(float flo, float fhi) {
    u32 d;
    asm("cvt.rn.bf16x2.f32 %0, %1, %2;" : "=r"(d) : "f"(fhi), "f"(flo));
    return d;
}
// Dekker split of a pair into hi bf16x2 + lo bf16x2 (residual)
__device__ __forceinline__ void split_pair(float f0, float f1, u32& hi, u32& lo) {
    u32 h = pack2(f0, f1);
    float h0 = __uint_as_float(h << 16);
    float h1 = __uint_as_float(h & 0xffff0000u);
    lo = pack2(f0 - h0, f1 - h1);
    hi = h;
}

// ---------------------------------------------------------------------------
// Kernel 0: split fp32 inputs (x and the 4 weight matrices) into bf16 hi/lo.
// ---------------------------------------------------------------------------
__global__ void split_inputs(const float* __restrict__ x,
                             const float* __restrict__ Wq, const float* __restrict__ Wk,
                             const float* __restrict__ Wv, const float* __restrict__ Wo) {
    int i = blockIdx.x * 256 + threadIdx.x;
    const float* src;
    __nv_bfloat16 *dh, *dl;
    int off;
    if (i < XPAIRS) {
        src = x; dh = g_xh; dl = g_xl; off = i;
    } else {
        int j = i - XPAIRS;
        int w = j / WPAIRS;
        off = j - w * WPAIRS;
        src = (w == 0) ? Wq : (w == 1) ? Wk : (w == 2) ? Wv : Wo;
        dh = g_wh[w]; dl = g_wl[w];
    }
    float2 v = ((const float2*)src)[off];
    u32 h, l;
    split_pair(v.x, v.y, h, l);
    ((u32*)dh)[off] = h;
    ((u32*)dl)[off] = l;
}

// ---------------------------------------------------------------------------
// Kernel 1: pack adjacency (int32 0/1) into transposed bitmask.
// ---------------------------------------------------------------------------
__global__ void pack_adj_kernel(const int* __restrict__ adj) {
    int gw = (blockIdx.x * blockDim.x + threadIdx.x) >> 5;
    int lane = threadIdx.x & 31;
    int r  = gw >> 7;
    int cw = gw & 127;
    int v = adj[(size_t)r * N_TOK + cw * 32 + lane];
    unsigned b = __ballot_sync(0xffffffffu, v != 0);
    if (lane == 0) g_adjT[(size_t)cw * N_TOK + r] = b;
}

// ---------------------------------------------------------------------------
// MMA GEMM mainloop: C[128x64] tile of A[4096,256] @ B[64,256]^T, 3-term bf16.
// ---------------------------------------------------------------------------
#define PROJ_MAINLOOP(Ah, Al, Bh, Bl, mt, nt)                                   \
    __shared__ __align__(16) __nv_bfloat16 sAh[128 * SROW], sAl[128 * SROW];    \
    __shared__ __align__(16) __nv_bfloat16 sBh[64 * SROW],  sBl[64 * SROW];     \
    const int tid = threadIdx.x;                                                \
    const int lane = tid & 31;                                                  \
    const int wp = tid >> 5;                                                    \
    float c[8][4];                                                              \
    _Pragma("unroll")                                                           \
    for (int ng = 0; ng < 8; ng++)                                              \
        c[ng][0] = c[ng][1] = c[ng][2] = c[ng][3] = 0.f;                        \
    const int ar0 = tid >> 2,         ad = tid & 3;                             \
    const int ar1 = (tid + 256) >> 2;                                           \
    const int br  = tid >> 2,         bd = tid & 3;                             \
    const u32 dAh = cvta_s(sAh), dAl = cvta_s(sAl);                             \
    const u32 dBh = cvta_s(sBh), dBl = cvta_s(sBl);                             \
    for (int kc = 0; kc < 8; kc++) {                                            \
        const int k0 = kc * 32;                                                 \
        __syncthreads();                                                        \
        cpasync16(dAh + ar0 * 80 + ad * 16,                                     \
                  Ah + (size_t)(mt * 128 + ar0) * E_DIM + k0 + ad * 8);         \
        cpasync16(dAh + ar1 * 80 + ad * 16,                                     \
                  Ah + (size_t)(mt * 128 + ar1) * E_DIM + k0 + ad * 8);         \
        cpasync16(dAl + ar0 * 80 + ad * 16,                                     \
                  Al + (size_t)(mt * 128 + ar0) * E_DIM + k0 + ad * 8);         \
        cpasync16(dAl + ar1 * 80 + ad * 16,                                     \
                  Al + (size_t)(mt * 128 + ar1) * E_DIM + k0 + ad * 8);         \
        cpasync16(dBh + br * 80 + bd * 16,                                      \
                  Bh + (size_t)(nt * 64 + br) * E_DIM + k0 + bd * 8);           \
        cpasync16(dBl + br * 80 + bd * 16,                                      \
                  Bl + (size_t)(nt * 64 + br) * E_DIM + k0 + bd * 8);           \
        cp_commit();                                                            \
        cp_wait<0>();                                                           \
        __syncthreads();                                                        \
        _Pragma("unroll")                                                       \
        for (int ks = 0; ks < 2; ks++) {                                        \
            u32 ah[4], al[4];                                                   \
            u32 ao = (wp * 16 + (lane & 15)) * 80 + ks * 32 + (lane >> 4) * 16; \
            ldsm_x4(ah, dAh + ao);                                              \
            ldsm_x4(al, dAl + ao);                                              \
            const u32 kof = (lane & 7) * 80 + ((lane >> 3) & 1) * 16 + ks * 32; \
            _Pragma("unroll")                                                   \
            for (int ng = 0; ng < 8; ng++) {                                    \
                u32 bh[2], bl[2];                                               \
                ldsm_x2(bh, dBh + kof + ng * 640);                              \
                ldsm_x2(bl, dBl + kof + ng * 640);                              \
                mma_bf16(c[ng], ah, bh);                                        \
                mma_bf16(c[ng], ah, bl);                                        \
                mma_bf16(c[ng], al, bh);                                        \
            }                                                                   \
        }                                                                       \
    }

// Q/K/V projections via MMA, grid (4, 32, 3): nt, mt, which.
__global__ void __launch_bounds__(256) proj_mma(const float* __restrict__ bq,
                                                const float* __restrict__ bk,
                                                const float* __restrict__ bv) {
    const int nt = blockIdx.x, mt = blockIdx.y, which = blockIdx.z;
    const __nv_bfloat16* Ah = g_xh;
    const __nv_bfloat16* Al = g_xl;
    const __nv_bfloat16* Bh = g_wh[which];
    const __nv_bfloat16* Bl = g_wl[which];
    const float* bias = (which == 0) ? bq : (which == 1) ? bk : bv;
    const float scale = (which == 0)
        ? 0.17677669529663688f * 1.4426950408889634f   // 1/sqrt(32) * log2(e)
        : 1.0f;
    __nv_bfloat16* Ch = (which == 0) ? g_qh : (which == 1) ? g_kh : g_vh;
    __nv_bfloat16* Cl = (which == 0) ? g_ql : (which == 1) ? g_kl : g_vl;

    PROJ_MAINLOOP(Ah, Al, Bh, Bl, mt, nt)

    const int r0 = mt * 128 + wp * 16 + (lane >> 2);
    const int r1 = r0 + 8;
#pragma unroll
    for (int ng = 0; ng < 8; ng++) {
        int col = nt * 64 + ng * 8 + 2 * (lane & 3);
        float b0 = bias[col], b1 = bias[col + 1];
        float v0 = (c[ng][0] + b0) * scale;
        float v1 = (c[ng][1] + b1) * scale;
        float v2 = (c[ng][2] + b0) * scale;
        float v3 = (c[ng][3] + b1) * scale;
        u32 h, l;
        split_pair(v0, v1, h, l);
        *(u32*)(Ch + (size_t)r0 * E_DIM + col) = h;
        *(u32*)(Cl + (size_t)r0 * E_DIM + col) = l;
        split_pair(v2, v3, h, l);
        *(u32*)(Ch + (size_t)r1 * E_DIM + col) = h;
        *(u32*)(Cl + (size_t)r1 * E_DIM + col) = l;
    }
}

// Output projection via MMA, grid (4, 32). A = attention output (pre-split).
__global__ void __launch_bounds__(256) out_mma(const float* __restrict__ bo,
                                               float* __restrict__ out) {
    const int nt = blockIdx.x, mt = blockIdx.y;

    PROJ_MAINLOOP(g_ah, g_al, g_wh[3], g_wl[3], mt, nt)

    const int r0 = mt * 128 + wp * 16 + (lane >> 2);
    const int r1 = r0 + 8;
#pragma unroll
    for (int ng = 0; ng < 8; ng++) {
        int col = nt * 64 + ng * 8 + 2 * (lane & 3);
        float b0 = bo[col], b1 = bo[col + 1];
        float2 s0 = make_float2(c[ng][0] + b0, c[ng][1] + b1);
        float2 s1 = make_float2(c[ng][2] + b0, c[ng][3] + b1);
        *(float2*)(out + (size_t)r0 * E_DIM + col) = s0;
        *(float2*)(out + (size_t)r1 * E_DIM + col) = s1;
    }
}

// ---------------------------------------------------------------------------
// Kernel 3: split-K(x4) tensor-core masked flash attention, max-free exp2
// softmax, cp.async double buffer, x4 ldmatrix, mask prefetch 1 tile ahead.
// Grid (64, 8, 4), 128 threads (4 warps) — the round-12 winning shape.
// Each split handles 16 key-tiles of 64, writes unnormalized O + l partials.
// ---------------------------------------------------------------------------
__global__ void __launch_bounds__(128) attn_mma_kernel() {
    __shared__ __align__(16) __nv_bfloat16 sKh[2][64 * SROW], sKl[2][64 * SROW];
    __shared__ __align__(16) __nv_bfloat16 sVh[2][64 * SROW], sVl[2][64 * SROW];

    const int tid = threadIdx.x;
    const int lane = tid & 31;
    const int wp = tid >> 5;
    const int h = blockIdx.y;
    const int z = blockIdx.z;
    const int qb = blockIdx.x * 64;
    const int jt0 = z * TILES_PER_SPLIT;   // this split's key-tile range

    const int row0 = tid >> 2, dp0 = tid & 3;
    const int row1 = (tid + 128) >> 2, dp1 = tid & 3;
    const int so0 = row0 * 80 + dp0 * 16;
    const int so1 = row1 * 80 + dp1 * 16;

    // ---- Stage Q tile (hi/lo) into stage-0 K buffers, build A-fragments ----
    {
        size_t gq0 = (size_t)(qb + row0) * E_DIM + h * D_HEAD + dp0 * 8;
        size_t gq1 = (size_t)(qb + row1) * E_DIM + h * D_HEAD + dp1 * 8;
        *(uint4*)((char*)sKh[0] + so0) = *(const uint4*)(g_qh + gq0);
        *(uint4*)((char*)sKh[0] + so1) = *(const uint4*)(g_qh + gq1);
        *(uint4*)((char*)sKl[0] + so0) = *(const uint4*)(g_ql + gq0);
        *(uint4*)((char*)sKl[0] + so1) = *(const uint4*)(g_ql + gq1);
    }
    __syncthreads();

    u32 qh[2][4], ql[2][4];
    {
        int arow = wp * 16 + (lane & 15);
        int acol = (lane >> 4) * 8;
        u32 bh = cvta_s(sKh[0]), bl = cvta_s(sKl[0]);
#pragma unroll
        for (int ks = 0; ks < 2; ks++) {
            u32 ao = arow * 80 + (ks * 16 + acol) * 2;
            ldsm_x4(qh[ks], bh + ao);
            ldsm_x4(ql[ks], bl + ao);
        }
    }
    __syncthreads();

    // ---- Prefetch this split's first key tile into stage 0 ----
    {
        size_t g0 = (size_t)(jt0 * 64 + row0) * E_DIM + h * D_HEAD + dp0 * 8;
        size_t g1 = (size_t)(jt0 * 64 + row1) * E_DIM + h * D_HEAD + dp1 * 8;
        u32 kh = cvta_s(sKh[0]), kl = cvta_s(sKl[0]);
        u32 vh = cvta_s(sVh[0]), vl = cvta_s(sVl[0]);
        cpasync16(kh + so0, g_kh + g0); cpasync16(kh + so1, g_kh + g1);
        cpasync16(kl + so0, g_kl + g0); cpasync16(kl + so1, g_kl + g1);
        cpasync16(vh + so0, g_vh + g0); cpasync16(vh + so1, g_vh + g1);
        cpasync16(vl + so0, g_vl + g0); cpasync16(vl + so1, g_vl + g1);
        cp_commit();
    }

    float o[4][4];
#pragma unroll
    for (int nd = 0; nd < 4; nd++)
        o[nd][0] = o[nd][1] = o[nd][2] = o[nd][3] = 0.f;
    float l0 = 0.f, l1 = 0.f;

    const int r0 = qb + wp * 16 + (lane >> 2);
    const int r1 = r0 + 8;

    const u32 kofs4 = (((lane >> 4) & 1) * 8 + (lane & 7)) * 80
                    + ((lane >> 3) & 1) * 16;
    const u32 vofs4 = (lane & 15) * 80 + ((lane >> 4) & 1) * 16;

    // Mask prefetch: registers hold tile jt's words, loaded one tile early.
    u32 w00 = g_adjT[(size_t)(jt0 * 2 + 0) * N_TOK + r0];
    u32 w01 = g_adjT[(size_t)(jt0 * 2 + 1) * N_TOK + r0];
    u32 w10 = g_adjT[(size_t)(jt0 * 2 + 0) * N_TOK + r1];
    u32 w11 = g_adjT[(size_t)(jt0 * 2 + 1) * N_TOK + r1];

    for (int jj = 0; jj < TILES_PER_SPLIT; jj++) {
        const int jt = jt0 + jj;
        const int cur = jj & 1, nxt = cur ^ 1;

        // Next-tile K/V + mask prefetch (issued a full tile ahead of use)
        u32 n00, n01, n10, n11;
        if (jj + 1 < TILES_PER_SPLIT) {
            size_t g0 = (size_t)((jt + 1) * 64 + row0) * E_DIM + h * D_HEAD + dp0 * 8;
            size_t g1 = (size_t)((jt + 1) * 64 + row1) * E_DIM + h * D_HEAD + dp1 * 8;
            u32 kh = cvta_s(sKh[nxt]), kl = cvta_s(sKl[nxt]);
            u32 vh = cvta_s(sVh[nxt]), vl = cvta_s(sVl[nxt]);
            cpasync16(kh + so0, g_kh + g0); cpasync16(kh + so1, g_kh + g1);
            cpasync16(kl + so0, g_kl + g0); cpasync16(kl + so1, g_kl + g1);
            cpasync16(vh + so0, g_vh + g0); cpasync16(vh + so1, g_vh + g1);
            cpasync16(vl + so0, g_vl + g0); cpasync16(vl + so1, g_vl + g1);
            cp_commit();
            n00 = g_adjT[(size_t)((jt + 1) * 2 + 0) * N_TOK + r0];
            n01 = g_adjT[(size_t)((jt + 1) * 2 + 1) * N_TOK + r0];
            n10 = g_adjT[(size_t)((jt + 1) * 2 + 0) * N_TOK + r1];
            n11 = g_adjT[(size_t)((jt + 1) * 2 + 1) * N_TOK + r1];
            cp_wait<1>();
        } else {
            n00 = n01 = n10 = n11 = 0;
            cp_wait<0>();
        }
        __syncthreads();

        const u32 kaH = cvta_s(sKh[cur]) + kofs4, kaL = cvta_s(sKl[cur]) + kofs4;
        const u32 vaH = cvta_s(sVh[cur]) + vofs4, vaL = cvta_s(sVl[cur]) + vofs4;

        // ---- S = Q @ K^T (4 n-frag pairs via x4, 2 k-steps, 3-term) ----
        float s[8][4];
#pragma unroll
        for (int np = 0; np < 4; np++) {
            s[2 * np][0] = s[2 * np][1] = s[2 * np][2] = s[2 * np][3] = 0.f;
            s[2 * np + 1][0] = s[2 * np + 1][1] = 0.f;
            s[2 * np + 1][2] = s[2 * np + 1][3] = 0.f;
#pragma unroll
            for (int ks = 0; ks < 2; ks++) {
                u32 bh[4], bl[4];
                u32 off = np * 1280 + ks * 32;
                ldsm_x4(bh, kaH + off);
                ldsm_x4(bl, kaL + off);
                mma_bf16(s[2 * np], qh[ks], bh);
                mma_bf16(s[2 * np], qh[ks], bl);
                mma_bf16(s[2 * np], ql[ks], bh);
                mma_bf16(s[2 * np + 1], qh[ks], bh + 2);
                mma_bf16(s[2 * np + 1], qh[ks], bl + 2);
                mma_bf16(s[2 * np + 1], ql[ks], bh + 2);
            }
        }

        // ---- mask + MAX-FREE softmax: p = exp2(s) ----
        const int sh2 = 2 * (lane & 3);
#pragma unroll
        for (int ng = 0; ng < 8; ng++) {
            u32 wr0 = (ng < 4) ? w00 : w01;
            u32 wr1 = (ng < 4) ? w10 : w11;
            int sh = (ng & 3) * 8 + sh2;
            if (!((wr0 >> sh) & 1))       s[ng][0] = -INFINITY;
            if (!((wr0 >> (sh + 1)) & 1)) s[ng][1] = -INFINITY;
            if (!((wr1 >> sh) & 1))       s[ng][2] = -INFINITY;
            if (!((wr1 >> (sh + 1)) & 1)) s[ng][3] = -INFINITY;
        }
#pragma unroll
        for (int ng = 0; ng < 8; ng++) {
            s[ng][0] = exp2f(s[ng][0]);
            s[ng][1] = exp2f(s[ng][1]);
            s[ng][2] = exp2f(s[ng][2]);
            s[ng][3] = exp2f(s[ng][3]);
            l0 += s[ng][0] + s[ng][1];
            l1 += s[ng][2] + s[ng][3];
        }

        // ---- O += P @ V (4 key-steps, dim-frag pairs via x4 trans) ----
#pragma unroll
        for (int ks = 0; ks < 4; ks++) {
            u32 ah[4], alo[4];
            split_pair(s[2 * ks][0],     s[2 * ks][1],     ah[0], alo[0]);
            split_pair(s[2 * ks][2],     s[2 * ks][3],     ah[1], alo[1]);
            split_pair(s[2 * ks + 1][0], s[2 * ks + 1][1], ah[2], alo[2]);
            split_pair(s[2 * ks + 1][2], s[2 * ks + 1][3], ah[3], alo[3]);
#pragma unroll
            for (int np = 0; np < 2; np++) {
                u32 bh[4], bl[4];
                u32 off = ks * 1280 + np * 32;
                ldsm_x4t(bh, vaH + off);
                ldsm_x4t(bl, vaL + off);
                mma_bf16(o[2 * np], ah, bh);
                mma_bf16(o[2 * np], ah, bl);
                mma_bf16(o[2 * np], alo, bh);
                mma_bf16(o[2 * np + 1], ah, bh + 2);
                mma_bf16(o[2 * np + 1], ah, bl + 2);
                mma_bf16(o[2 * np + 1], alo, bh + 2);
            }
        }
        w00 = n00; w01 = n01; w10 = n10; w11 = n11;
        __syncthreads();
    }

    // ---- write unnormalized partials (max-free: no m, no alpha) ----
    l0 += __shfl_xor_sync(0xffffffffu, l0, 1);
    l0 += __shfl_xor_sync(0xffffffffu, l0, 2);
    l1 += __shfl_xor_sync(0xffffffffu, l1, 1);
    l1 += __shfl_xor_sync(0xffffffffu, l1, 2);
    const int idx0 = h * N_TOK + r0;
    const int idx1 = h * N_TOK + r1;
    if ((lane & 3) == 0) {
        g_pl[z][idx0] = l0;
        g_pl[z][idx1] = l1;
    }
    float* p0 = &g_po[z][(size_t)idx0 * D_HEAD];
    float* p1 = &g_po[z][(size_t)idx1 * D_HEAD];
#pragma unroll
    for (int nd = 0; nd < 4; nd++) {
        int cn = nd * 8 + 2 * (lane & 3);
        *(float2*)(p0 + cn) = make_float2(o[nd][0], o[nd][1]);
        *(float2*)(p1 + cn) = make_float2(o[nd][2], o[nd][3]);
    }
}

// ---------------------------------------------------------------------------
// Kernel 4: combine the 4 split partials, normalize, write hi/lo bf16 split.
// One thread per (h,row,4-dim chunk): H*N*8 = 262144 threads.
// ---------------------------------------------------------------------------
__global__ void combine_kernel() {
    int c = blockIdx.x * 256 + threadIdx.x;
    int cc = c & 7;
    int idx = c >> 3;                 // h*N + r
    float lsum = 0.f;
#pragma unroll
    for (int s = 0; s < NSPLIT; s++) lsum += g_pl[s][idx];
    float inv = 1.f / lsum;
    float v0 = 0.f, v1 = 0.f, v2 = 0.f, v3 = 0.f;
#pragma unroll
    for (int s = 0; s < NSPLIT; s++) {
        float4 a = *(const float4*)&g_po[s][(size_t)idx * D_HEAD + cc * 4];
        v0 += a.x; v1 += a.y; v2 += a.z; v3 += a.w;
    }
    v0 *= inv; v1 *= inv; v2 *= inv; v3 *= inv;
    int r = idx & (N_TOK - 1);
    int h = idx >> 12;
    size_t off = (size_t)r * E_DIM + h * D_HEAD + cc * 4;
    u32 hh, ll;
    split_pair(v0, v1, hh, ll);
    *(u32*)(g_ah + off) = hh;
    *(u32*)(g_al + off) = ll;
    split_pair(v2, v3, hh, ll);
    *(u32*)(g_ah + off + 2) = hh;
    *(u32*)(g_al + off + 2) = ll;
}

// ---------------------------------------------------------------------------
extern "C" void kernel_launch(void* const* d_in, const int* in_sizes, int n_in,
                              void* d_out, int out_size) {
    const float* x   = (const float*)d_in[0];
    const int*   adj = (const int*)d_in[1];
    const float* Wq  = (const float*)d_in[2];
    const float* bq  = (const float*)d_in[3];
    const float* Wk  = (const float*)d_in[4];
    const float* bk  = (const float*)d_in[5];
    const float* Wv  = (const float*)d_in[6];
    const float* bv  = (const float*)d_in[7];
    const float* Wo  = (const float*)d_in[8];
    const float* bo  = (const float*)d_in[9];
    float* out = (float*)d_out;

    split_inputs<<<(XPAIRS + 4 * WPAIRS) / 256, 256>>>(x, Wq, Wk, Wv, Wo);

    pack_adj_kernel<<<(N_TOK * 128) / 8, 256>>>(adj);

    proj_mma<<<dim3(4, 32, 3), 256>>>(bq, bk, bv);

    attn_mma_kernel<<<dim3(N_TOK / 64, H_NUM, NSPLIT), 128>>>();

    combine_kernel<<<(H_NUM * N_TOK * 8) / 256, 256>>>();

    out_mma<<<dim3(4, 32), 256>>>(bo, out);
}

// round 15
// speedup vs baseline: 1.0684x; 1.0188x over previous
#include <cuda_runtime.h>
#include <cuda_bf16.h>
#include <math.h>
#include <stdint.h>

// Problem constants: B=1, N=4096, E=256, H=8, D=32
#define N_TOK 4096
#define E_DIM 256
#define H_NUM 8
#define D_HEAD 32
#define SROW 40          // bf16 elems per smem row (80 B: conflict-free ldmatrix)
#define XPAIRS (N_TOK * E_DIM / 2)
#define WPAIRS (E_DIM * E_DIM / 2)
#define NSPLIT 2
#define TPS (64 / NSPLIT)   // 32 key-tiles of 64 keys per split

typedef unsigned int u32;

// Scratch (device globals; no allocation allowed)
__device__ __nv_bfloat16 g_xh[N_TOK * E_DIM], g_xl[N_TOK * E_DIM];   // split x
__device__ __nv_bfloat16 g_wh[4][E_DIM * E_DIM], g_wl[4][E_DIM * E_DIM]; // Wq,Wk,Wv,Wo
__device__ __nv_bfloat16 g_qh[N_TOK * E_DIM], g_ql[N_TOK * E_DIM];
__device__ __nv_bfloat16 g_kh[N_TOK * E_DIM], g_kl[N_TOK * E_DIM];
__device__ __nv_bfloat16 g_vh[N_TOK * E_DIM], g_vl[N_TOK * E_DIM];
__device__ __nv_bfloat16 g_ah[N_TOK * E_DIM], g_al[N_TOK * E_DIM];   // attn out (split)
// Bitmask: g_adjT[cw * N_TOK + r], bit j = adjacency[r][cw*32+j] != 0
__device__ unsigned g_adjT[(N_TOK / 32) * N_TOK];
// Split-K partials (max-free: only unnormalized O and l needed)
__device__ float g_po[NSPLIT][H_NUM * N_TOK * D_HEAD];
__device__ float g_pl[NSPLIT][H_NUM * N_TOK];

// ---------------------------------------------------------------------------
// MMA / ldmatrix / cp.async helpers
// ---------------------------------------------------------------------------
__device__ __forceinline__ u32 cvta_s(const void* p) {
    return (u32)__cvta_generic_to_shared(p);
}
__device__ __forceinline__ void ldsm_x4(u32* r, u32 a) {
    asm volatile("ldmatrix.sync.aligned.m8n8.x4.shared.b16 {%0,%1,%2,%3}, [%4];"
        : "=r"(r[0]), "=r"(r[1]), "=r"(r[2]), "=r"(r[3]) : "r"(a));
}
__device__ __forceinline__ void ldsm_x4t(u32* r, u32 a) {
    asm volatile("ldmatrix.sync.aligned.m8n8.x4.trans.shared.b16 {%0,%1,%2,%3}, [%4];"
        : "=r"(r[0]), "=r"(r[1]), "=r"(r[2]), "=r"(r[3]) : "r"(a));
}
__device__ __forceinline__ void ldsm_x2(u32* r, u32 a) {
    asm volatile("ldmatrix.sync.aligned.m8n8.x2.shared.b16 {%0,%1}, [%2];"
        : "=r"(r[0]), "=r"(r[1]) : "r"(a));
}
__device__ __forceinline__ void mma_bf16(float* c, const u32* a, const u32* b) {
    asm volatile("mma.sync.aligned.m16n8k16.row.col.f32.bf16.bf16.f32 "
        "{%0,%1,%2,%3}, {%4,%5,%6,%7}, {%8,%9}, {%0,%1,%2,%3};"
        : "+f"(c[0]), "+f"(c[1]), "+f"(c[2]), "+f"(c[3])
        : "r"(a[0]), "r"(a[1]), "r"(a[2]), "r"(a[3]), "r"(b[0]), "r"(b[1]));
}
__device__ __forceinline__ void cpasync16(u32 dst, const void* src) {
    asm volatile("cp.async.ca.shared.global [%0], [%1], 16;" :: "r"(dst), "l"(src));
}
__device__ __forceinline__ void cp_commit() {
    asm volatile("cp.async.commit_group;");
}
template <int N>
__device__ __forceinline__ void cp_wait() {
    asm volatile("cp.async.wait_group %0;" :: "n"(N));
}
// pack2(f_low, f_high): bf16x2 reg, low half = first element
__device__ __forceinline__ u32 pack2(float flo, float fhi) {
    u32 d;
    asm("cvt.rn.bf16x2.f32 %0, %1, %2;" : "=r"(d) : "f"(fhi), "f"(flo));
    return d;
}
// Dekker split of a pair into hi bf16x2 + lo bf16x2 (residual)
__device__ __forceinline__ void split_pair(float f0, float f1, u32& hi, u32& lo) {
    u32 h = pack2(f0, f1);
    float h0 = __uint_as_float(h << 16);
    float h1 = __uint_as_float(h & 0xffff0000u);
    lo = pack2(f0 - h0, f1 - h1);
    hi = h;
}

// ---------------------------------------------------------------------------
// Kernel 0: split fp32 inputs (x and the 4 weight matrices) into bf16 hi/lo.
// ---------------------------------------------------------------------------
__global__ void split_inputs(const float* __restrict__ x,
                             const float* __restrict__ Wq, const float* __restrict__ Wk,
                             const float* __restrict__ Wv, const float* __restrict__ Wo) {
    int i = blockIdx.x * 256 + threadIdx.x;
    const float* src;
    __nv_bfloat16 *dh, *dl;
    int off;
    if (i < XPAIRS) {
        src = x; dh = g_xh; dl = g_xl; off = i;
    } else {
        int j = i - XPAIRS;
        int w = j / WPAIRS;
        off = j - w * WPAIRS;
        src = (w == 0) ? Wq : (w == 1) ? Wk : (w == 2) ? Wv : Wo;
        dh = g_wh[w]; dl = g_wl[w];
    }
    float2 v = ((const float2*)src)[off];
    u32 h, l;
    split_pair(v.x, v.y, h, l);
    ((u32*)dh)[off] = h;
    ((u32*)dl)[off] = l;
}

// ---------------------------------------------------------------------------
// Kernel 1: pack adjacency (int32 0/1) into transposed bitmask.
// ---------------------------------------------------------------------------
__global__ void pack_adj_kernel(const int* __restrict__ adj) {
    int gw = (blockIdx.x * blockDim.x + threadIdx.x) >> 5;
    int lane = threadIdx.x & 31;
    int r  = gw >> 7;
    int cw = gw & 127;
    int v = adj[(size_t)r * N_TOK + cw * 32 + lane];
    unsigned b = __ballot_sync(0xffffffffu, v != 0);
    if (lane == 0) g_adjT[(size_t)cw * N_TOK + r] = b;
}

// ---------------------------------------------------------------------------
// MMA GEMM mainloop: C[128x64] tile of A[4096,256] @ B[64,256]^T, 3-term bf16.
// ---------------------------------------------------------------------------
#define PROJ_MAINLOOP(Ah, Al, Bh, Bl, mt, nt)                                   \
    __shared__ __align__(16) __nv_bfloat16 sAh[128 * SROW], sAl[128 * SROW];    \
    __shared__ __align__(16) __nv_bfloat16 sBh[64 * SROW],  sBl[64 * SROW];     \
    const int tid = threadIdx.x;                                                \
    const int lane = tid & 31;                                                  \
    const int wp = tid >> 5;                                                    \
    float c[8][4];                                                              \
    _Pragma("unroll")                                                           \
    for (int ng = 0; ng < 8; ng++)                                              \
        c[ng][0] = c[ng][1] = c[ng][2] = c[ng][3] = 0.f;                        \
    const int ar0 = tid >> 2,         ad = tid & 3;                             \
    const int ar1 = (tid + 256) >> 2;                                           \
    const int br  = tid >> 2,         bd = tid & 3;                             \
    const u32 dAh = cvta_s(sAh), dAl = cvta_s(sAl);                             \
    const u32 dBh = cvta_s(sBh), dBl = cvta_s(sBl);                             \
    for (int kc = 0; kc < 8; kc++) {                                            \
        const int k0 = kc * 32;                                                 \
        __syncthreads();                                                        \
        cpasync16(dAh + ar0 * 80 + ad * 16,                                     \
                  Ah + (size_t)(mt * 128 + ar0) * E_DIM + k0 + ad * 8);         \
        cpasync16(dAh + ar1 * 80 + ad * 16,                                     \
                  Ah + (size_t)(mt * 128 + ar1) * E_DIM + k0 + ad * 8);         \
        cpasync16(dAl + ar0 * 80 + ad * 16,                                     \
                  Al + (size_t)(mt * 128 + ar0) * E_DIM + k0 + ad * 8);         \
        cpasync16(dAl + ar1 * 80 + ad * 16,                                     \
                  Al + (size_t)(mt * 128 + ar1) * E_DIM + k0 + ad * 8);         \
        cpasync16(dBh + br * 80 + bd * 16,                                      \
                  Bh + (size_t)(nt * 64 + br) * E_DIM + k0 + bd * 8);           \
        cpasync16(dBl + br * 80 + bd * 16,                                      \
                  Bl + (size_t)(nt * 64 + br) * E_DIM + k0 + bd * 8);           \
        cp_commit();                                                            \
        cp_wait<0>();                                                           \
        __syncthreads();                                                        \
        _Pragma("unroll")                                                       \
        for (int ks = 0; ks < 2; ks++) {                                        \
            u32 ah[4], al[4];                                                   \
            u32 ao = (wp * 16 + (lane & 15)) * 80 + ks * 32 + (lane >> 4) * 16; \
            ldsm_x4(ah, dAh + ao);                                              \
            ldsm_x4(al, dAl + ao);                                              \
            const u32 kof = (lane & 7) * 80 + ((lane >> 3) & 1) * 16 + ks * 32; \
            _Pragma("unroll")                                                   \
            for (int ng = 0; ng < 8; ng++) {                                    \
                u32 bh[2], bl[2];                                               \
                ldsm_x2(bh, dBh + kof + ng * 640);                              \
                ldsm_x2(bl, dBl + kof + ng * 640);                              \
                mma_bf16(c[ng], ah, bh);                                        \
                mma_bf16(c[ng], ah, bl);                                        \
                mma_bf16(c[ng], al, bh);                                        \
            }                                                                   \
        }                                                                       \
    }

// Q/K/V projections via MMA, grid (4, 32, 3): nt, mt, which.
__global__ void __launch_bounds__(256) proj_mma(const float* __restrict__ bq,
                                                const float* __restrict__ bk,
                                                const float* __restrict__ bv) {
    const int nt = blockIdx.x, mt = blockIdx.y, which = blockIdx.z;
    const __nv_bfloat16* Ah = g_xh;
    const __nv_bfloat16* Al = g_xl;
    const __nv_bfloat16* Bh = g_wh[which];
    const __nv_bfloat16* Bl = g_wl[which];
    const float* bias = (which == 0) ? bq : (which == 1) ? bk : bv;
    const float scale = (which == 0)
        ? 0.17677669529663688f * 1.4426950408889634f   // 1/sqrt(32) * log2(e)
        : 1.0f;
    __nv_bfloat16* Ch = (which == 0) ? g_qh : (which == 1) ? g_kh : g_vh;
    __nv_bfloat16* Cl = (which == 0) ? g_ql : (which == 1) ? g_kl : g_vl;

    PROJ_MAINLOOP(Ah, Al, Bh, Bl, mt, nt)

    const int r0 = mt * 128 + wp * 16 + (lane >> 2);
    const int r1 = r0 + 8;
#pragma unroll
    for (int ng = 0; ng < 8; ng++) {
        int col = nt * 64 + ng * 8 + 2 * (lane & 3);
        float b0 = bias[col], b1 = bias[col + 1];
        float v0 = (c[ng][0] + b0) * scale;
        float v1 = (c[ng][1] + b1) * scale;
        float v2 = (c[ng][2] + b0) * scale;
        float v3 = (c[ng][3] + b1) * scale;
        u32 h, l;
        split_pair(v0, v1, h, l);
        *(u32*)(Ch + (size_t)r0 * E_DIM + col) = h;
        *(u32*)(Cl + (size_t)r0 * E_DIM + col) = l;
        split_pair(v2, v3, h, l);
        *(u32*)(Ch + (size_t)r1 * E_DIM + col) = h;
        *(u32*)(Cl + (size_t)r1 * E_DIM + col) = l;
    }
}

// Output projection via MMA, grid (4, 32). A = attention output (pre-split).
__global__ void __launch_bounds__(256) out_mma(const float* __restrict__ bo,
                                               float* __restrict__ out) {
    const int nt = blockIdx.x, mt = blockIdx.y;

    PROJ_MAINLOOP(g_ah, g_al, g_wh[3], g_wl[3], mt, nt)

    const int r0 = mt * 128 + wp * 16 + (lane >> 2);
    const int r1 = r0 + 8;
#pragma unroll
    for (int ng = 0; ng < 8; ng++) {
        int col = nt * 64 + ng * 8 + 2 * (lane & 3);
        float b0 = bo[col], b1 = bo[col + 1];
        float2 s0 = make_float2(c[ng][0] + b0, c[ng][1] + b1);
        float2 s1 = make_float2(c[ng][2] + b0, c[ng][3] + b1);
        *(float2*)(out + (size_t)r0 * E_DIM + col) = s0;
        *(float2*)(out + (size_t)r1 * E_DIM + col) = s1;
    }
}

// ---------------------------------------------------------------------------
// Phase macros for the pipelined attention mainloop
// ---------------------------------------------------------------------------
// S(tile) = Q @ K^T into s[8][4], from K buffers addressed by kaH_/kaL_.
#define S_PHASE(kaH_, kaL_)                                                     \
    _Pragma("unroll")                                                           \
    for (int np = 0; np < 4; np++) {                                            \
        s[2 * np][0] = s[2 * np][1] = s[2 * np][2] = s[2 * np][3] = 0.f;        \
        s[2 * np + 1][0] = s[2 * np + 1][1] = 0.f;                              \
        s[2 * np + 1][2] = s[2 * np + 1][3] = 0.f;                              \
        _Pragma("unroll")                                                       \
        for (int ks = 0; ks < 2; ks++) {                                        \
            u32 bh[4], bl[4];                                                   \
            u32 off = np * 1280 + ks * 32;                                      \
            ldsm_x4(bh, (kaH_) + off);                                          \
            ldsm_x4(bl, (kaL_) + off);                                          \
            mma_bf16(s[2 * np], qh[ks], bh);                                    \
            mma_bf16(s[2 * np], qh[ks], bl);                                    \
            mma_bf16(s[2 * np], ql[ks], bh);                                    \
            mma_bf16(s[2 * np + 1], qh[ks], bh + 2);                            \
            mma_bf16(s[2 * np + 1], qh[ks], bl + 2);                            \
            mma_bf16(s[2 * np + 1], ql[ks], bh + 2);                            \
        }                                                                       \
    }

// mask + max-free exp2 + pack s into persistent P fragments paH/paL, update l.
#define EXP2_PACK(w00_, w01_, w10_, w11_)                                       \
    {                                                                           \
        const int sh2 = 2 * (lane & 3);                                         \
        _Pragma("unroll")                                                       \
        for (int ng = 0; ng < 8; ng++) {                                        \
            u32 wr0 = (ng < 4) ? (w00_) : (w01_);                               \
            u32 wr1 = (ng < 4) ? (w10_) : (w11_);                               \
            int sh = (ng & 3) * 8 + sh2;                                        \
            if (!((wr0 >> sh) & 1))       s[ng][0] = -INFINITY;                 \
            if (!((wr0 >> (sh + 1)) & 1)) s[ng][1] = -INFINITY;                 \
            if (!((wr1 >> sh) & 1))       s[ng][2] = -INFINITY;                 \
            if (!((wr1 >> (sh + 1)) & 1)) s[ng][3] = -INFINITY;                 \
        }                                                                       \
        _Pragma("unroll")                                                       \
        for (int ng = 0; ng < 8; ng++) {                                        \
            s[ng][0] = exp2f(s[ng][0]);                                         \
            s[ng][1] = exp2f(s[ng][1]);                                         \
            s[ng][2] = exp2f(s[ng][2]);                                         \
            s[ng][3] = exp2f(s[ng][3]);                                         \
            l0 += s[ng][0] + s[ng][1];                                          \
            l1 += s[ng][2] + s[ng][3];                                          \
        }                                                                       \
        _Pragma("unroll")                                                       \
        for (int ks = 0; ks < 4; ks++) {                                        \
            split_pair(s[2 * ks][0],     s[2 * ks][1],     paH[ks][0], paL[ks][0]); \
            split_pair(s[2 * ks][2],     s[2 * ks][3],     paH[ks][1], paL[ks][1]); \
            split_pair(s[2 * ks + 1][0], s[2 * ks + 1][1], paH[ks][2], paL[ks][2]); \
            split_pair(s[2 * ks + 1][2], s[2 * ks + 1][3], paH[ks][3], paL[ks][3]); \
        }                                                                       \
    }

// O += P @ V using persistent paH/paL, from V buffers addressed by vaH_/vaL_.
#define PV_PHASE(vaH_, vaL_)                                                    \
    _Pragma("unroll")                                                           \
    for (int ks = 0; ks < 4; ks++) {                                            \
        _Pragma("unroll")                                                       \
        for (int np = 0; np < 2; np++) {                                        \
            u32 bh[4], bl[4];                                                   \
            u32 off = ks * 1280 + np * 32;                                      \
            ldsm_x4t(bh, (vaH_) + off);                                         \
            ldsm_x4t(bl, (vaL_) + off);                                         \
            mma_bf16(o[2 * np], paH[ks], bh);                                   \
            mma_bf16(o[2 * np], paH[ks], bl);                                   \
            mma_bf16(o[2 * np], paL[ks], bh);                                   \
            mma_bf16(o[2 * np + 1], paH[ks], bh + 2);                           \
            mma_bf16(o[2 * np + 1], paH[ks], bl + 2);                           \
            mma_bf16(o[2 * np + 1], paL[ks], bh + 2);                           \
        }                                                                       \
    }

// Issue the 8 cp.asyncs staging key tile `t` into buffer stage `st`.
#define STAGE_TILE(t, st)                                                       \
    {                                                                           \
        size_t g0 = (size_t)((t) * 64 + row0) * E_DIM + h * D_HEAD + dp0 * 8;   \
        size_t g1 = (size_t)((t) * 64 + row1) * E_DIM + h * D_HEAD + dp1 * 8;   \
        u32 kh = cvta_s(sKh[st]), kl = cvta_s(sKl[st]);                         \
        u32 vh = cvta_s(sVh[st]), vl = cvta_s(sVl[st]);                         \
        cpasync16(kh + so0, g_kh + g0); cpasync16(kh + so1, g_kh + g1);         \
        cpasync16(kl + so0, g_kl + g0); cpasync16(kl + so1, g_kl + g1);         \
        cpasync16(vh + so0, g_vh + g0); cpasync16(vh + so1, g_vh + g1);         \
        cpasync16(vl + so0, g_vl + g0); cpasync16(vl + so1, g_vl + g1);         \
        cp_commit();                                                            \
    }

// ---------------------------------------------------------------------------
// Kernel 3: split-K(x2) tensor-core masked flash attention, max-free exp2
// softmax, SOFTWARE-PIPELINED: iteration jj issues PV(jj) + S(jj+1) as one
// contiguous 96-MMA tensor burst, then does exp2/pack(jj+1) while the tensor
// pipe drains. K runs one tile ahead of V. Grid (64, 8, 2), 128 threads.
// ---------------------------------------------------------------------------
__global__ void __launch_bounds__(128) attn_mma_kernel() {
    __shared__ __align__(16) __nv_bfloat16 sKh[2][64 * SROW], sKl[2][64 * SROW];
    __shared__ __align__(16) __nv_bfloat16 sVh[2][64 * SROW], sVl[2][64 * SROW];

    const int tid = threadIdx.x;
    const int lane = tid & 31;
    const int wp = tid >> 5;
    const int h = blockIdx.y;
    const int z = blockIdx.z;
    const int qb = blockIdx.x * 64;
    const int jt0 = z * TPS;

    const int row0 = tid >> 2, dp0 = tid & 3;
    const int row1 = (tid + 128) >> 2, dp1 = tid & 3;
    const int so0 = row0 * 80 + dp0 * 16;
    const int so1 = row1 * 80 + dp1 * 16;

    // ---- Stage Q tile (hi/lo) into stage-0 K buffers, build A-fragments ----
    {
        size_t gq0 = (size_t)(qb + row0) * E_DIM + h * D_HEAD + dp0 * 8;
        size_t gq1 = (size_t)(qb + row1) * E_DIM + h * D_HEAD + dp1 * 8;
        *(uint4*)((char*)sKh[0] + so0) = *(const uint4*)(g_qh + gq0);
        *(uint4*)((char*)sKh[0] + so1) = *(const uint4*)(g_qh + gq1);
        *(uint4*)((char*)sKl[0] + so0) = *(const uint4*)(g_ql + gq0);
        *(uint4*)((char*)sKl[0] + so1) = *(const uint4*)(g_ql + gq1);
    }
    __syncthreads();

    u32 qh[2][4], ql[2][4];
    {
        int arow = wp * 16 + (lane & 15);
        int acol = (lane >> 4) * 8;
        u32 bh = cvta_s(sKh[0]), bl = cvta_s(sKl[0]);
#pragma unroll
        for (int ks = 0; ks < 2; ks++) {
            u32 ao = arow * 80 + (ks * 16 + acol) * 2;
            ldsm_x4(qh[ks], bh + ao);
            ldsm_x4(ql[ks], bl + ao);
        }
    }
    __syncthreads();

    // ---- Prefetch tiles jt0 -> stage0 and jt0+1 -> stage1 (2 groups) ----
    STAGE_TILE(jt0, 0)
    STAGE_TILE(jt0 + 1, 1)

    float o[4][4];
#pragma unroll
    for (int nd = 0; nd < 4; nd++)
        o[nd][0] = o[nd][1] = o[nd][2] = o[nd][3] = 0.f;
    float l0 = 0.f, l1 = 0.f;
    float s[8][4];
    u32 paH[4][4], paL[4][4];

    const int r0 = qb + wp * 16 + (lane >> 2);
    const int r1 = r0 + 8;

    const u32 kofs4 = (((lane >> 4) & 1) * 8 + (lane & 7)) * 80
                    + ((lane >> 3) & 1) * 16;
    const u32 vofs4 = (lane & 15) * 80 + ((lane >> 4) & 1) * 16;
    const u32 kaH[2] = {cvta_s(sKh[0]) + kofs4, cvta_s(sKh[1]) + kofs4};
    const u32 kaL[2] = {cvta_s(sKl[0]) + kofs4, cvta_s(sKl[1]) + kofs4};
    const u32 vaH[2] = {cvta_s(sVh[0]) + vofs4, cvta_s(sVh[1]) + vofs4};
    const u32 vaL[2] = {cvta_s(sVl[0]) + vofs4, cvta_s(sVl[1]) + vofs4};

    // ---- Prologue: S(jt0) + exp2 -> P(jt0) (masks for jt0 loaded first) ----
    {
        u32 w00 = g_adjT[(size_t)(jt0 * 2 + 0) * N_TOK + r0];
        u32 w01 = g_adjT[(size_t)(jt0 * 2 + 1) * N_TOK + r0];
        u32 w10 = g_adjT[(size_t)(jt0 * 2 + 0) * N_TOK + r1];
        u32 w11 = g_adjT[(size_t)(jt0 * 2 + 1) * N_TOK + r1];
        cp_wait<1>();          // stage0 (tile jt0) resident; stage1 may pend
        __syncthreads();
        S_PHASE(kaH[0], kaL[0])
        EXP2_PACK(w00, w01, w10, w11)
    }

    // ---- Pipelined mainloop: iteration jj does PV(jj) and S(jj+1) ----
    for (int jj = 0; jj < TPS - 1; jj++) {
        const int jt = jt0 + jj;
        const int cur = jj & 1, nxt = cur ^ 1;

        cp_wait<0>();          // tile jj+1 resident in stage nxt
        __syncthreads();

        // masks for tile jj+1 (used at end of this iteration; L2-resident)
        u32 w00 = g_adjT[(size_t)((jt + 1) * 2 + 0) * N_TOK + r0];
        u32 w01 = g_adjT[(size_t)((jt + 1) * 2 + 1) * N_TOK + r0];
        u32 w10 = g_adjT[(size_t)((jt + 1) * 2 + 0) * N_TOK + r1];
        u32 w11 = g_adjT[(size_t)((jt + 1) * 2 + 1) * N_TOK + r1];

        // One contiguous tensor burst: PV(jj) [V cur, P regs] + S(jj+1) [K nxt]
        PV_PHASE(vaH[cur], vaL[cur])
        S_PHASE(kaH[nxt], kaL[nxt])

        __syncthreads();       // all warps done reading stage cur (V and old K)
        if (jj + 2 < TPS) STAGE_TILE(jt + 2, cur)

        // exp2/mask/pack for tile jj+1 while the tensor pipe drains PV+S
        EXP2_PACK(w00, w01, w10, w11)
    }

    // ---- Epilogue: PV(last tile); V resides in stage (TPS-1)&1 ----
    PV_PHASE(vaH[(TPS - 1) & 1], vaL[(TPS - 1) & 1])

    // ---- write unnormalized partials (max-free: no m, no alpha) ----
    l0 += __shfl_xor_sync(0xffffffffu, l0, 1);
    l0 += __shfl_xor_sync(0xffffffffu, l0, 2);
    l1 += __shfl_xor_sync(0xffffffffu, l1, 1);
    l1 += __shfl_xor_sync(0xffffffffu, l1, 2);
    const int idx0 = h * N_TOK + r0;
    const int idx1 = h * N_TOK + r1;
    if ((lane & 3) == 0) {
        g_pl[z][idx0] = l0;
        g_pl[z][idx1] = l1;
    }
    float* p0 = &g_po[z][(size_t)idx0 * D_HEAD];
    float* p1 = &g_po[z][(size_t)idx1 * D_HEAD];
#pragma unroll
    for (int nd = 0; nd < 4; nd++) {
        int cn = nd * 8 + 2 * (lane & 3);
        *(float2*)(p0 + cn) = make_float2(o[nd][0], o[nd][1]);
        *(float2*)(p1 + cn) = make_float2(o[nd][2], o[nd][3]);
    }
}

// ---------------------------------------------------------------------------
// Kernel 4: combine the split partials, normalize, write hi/lo bf16 split.
// One thread per (h,row,4-dim chunk): H*N*8 = 262144 threads.
// ---------------------------------------------------------------------------
__global__ void combine_kernel() {
    int c = blockIdx.x * 256 + threadIdx.x;
    int cc = c & 7;
    int idx = c >> 3;                 // h*N + r
    float lsum = 0.f;
#pragma unroll
    for (int s = 0; s < NSPLIT; s++) lsum += g_pl[s][idx];
    float inv = 1.f / lsum;
    float v0 = 0.f, v1 = 0.f, v2 = 0.f, v3 = 0.f;
#pragma unroll
    for (int s = 0; s < NSPLIT; s++) {
        float4 a = *(const float4*)&g_po[s][(size_t)idx * D_HEAD + cc * 4];
        v0 += a.x; v1 += a.y; v2 += a.z; v3 += a.w;
    }
    v0 *= inv; v1 *= inv; v2 *= inv; v3 *= inv;
    int r = idx & (N_TOK - 1);
    int h = idx >> 12;
    size_t off = (size_t)r * E_DIM + h * D_HEAD + cc * 4;
    u32 hh, ll;
    split_pair(v0, v1, hh, ll);
    *(u32*)(g_ah + off) = hh;
    *(u32*)(g_al + off) = ll;
    split_pair(v2, v3, hh, ll);
    *(u32*)(g_ah + off + 2) = hh;
    *(u32*)(g_al + off + 2) = ll;
}

// ---------------------------------------------------------------------------
extern "C" void kernel_launch(void* const* d_in, const int* in_sizes, int n_in,
                              void* d_out, int out_size) {
    const float* x   = (const float*)d_in[0];
    const int*   adj = (const int*)d_in[1];
    const float* Wq  = (const float*)d_in[2];
    const float* bq  = (const float*)d_in[3];
    const float* Wk  = (const float*)d_in[4];
    const float* bk  = (const float*)d_in[5];
    const float* Wv  = (const float*)d_in[6];
    const float* bv  = (const float*)d_in[7];
    const float* Wo  = (const float*)d_in[8];
    const float* bo  = (const float*)d_in[9];
    float* out = (float*)d_out;

    split_inputs<<<(XPAIRS + 4 * WPAIRS) / 256, 256>>>(x, Wq, Wk, Wv, Wo);

    pack_adj_kernel<<<(N_TOK * 128) / 8, 256>>>(adj);

    proj_mma<<<dim3(4, 32, 3), 256>>>(bq, bk, bv);

    attn_mma_kernel<<<dim3(N_TOK / 64, H_NUM, NSPLIT), 128>>>();

    combine_kernel<<<(H_NUM * N_TOK * 8) / 256, 256>>>();

    out_mma<<<dim3(4, 32), 256>>>(bo, out);
}

// round 17
// speedup vs baseline: 1.2238x; 1.1454x over previous
#include <cuda_runtime.h>
#include <cuda_bf16.h>
#include <math.h>
#include <stdint.h>

// Problem constants: B=1, N=4096, E=256, H=8, D=32
#define N_TOK 4096
#define E_DIM 256
#define H_NUM 8
#define D_HEAD 32
#define SROW 40          // bf16 elems per smem row (80 B: conflict-free ldmatrix)
#define NSPLIT 2
#define TPS (64 / NSPLIT)   // 32 key-tiles of 64 keys per split
#define XQUADS (N_TOK * E_DIM / 4)        // 262144 float4s of x
#define WQUADS (E_DIM * E_DIM / 4)        // 16384 float4s per weight matrix
#define SPLIT_BLKS ((XQUADS + 4 * WQUADS) / 256)   // (262144+65536)/256 = 1280
#define PACK_BLKS (N_TOK * 32 / 8)                 // 16384 (8 warps/block)

typedef unsigned int u32;

// Scratch (device globals; no allocation allowed)
__device__ __nv_bfloat16 g_xh[N_TOK * E_DIM], g_xl[N_TOK * E_DIM];   // split x
__device__ __nv_bfloat16 g_wh[4][E_DIM * E_DIM], g_wl[4][E_DIM * E_DIM]; // Wq,Wk,Wv,Wo
__device__ __nv_bfloat16 g_qh[N_TOK * E_DIM], g_ql[N_TOK * E_DIM];
__device__ __nv_bfloat16 g_kh[N_TOK * E_DIM], g_kl[N_TOK * E_DIM];
__device__ __nv_bfloat16 g_vh[N_TOK * E_DIM], g_vl[N_TOK * E_DIM];
__device__ __nv_bfloat16 g_ah[N_TOK * E_DIM], g_al[N_TOK * E_DIM];   // attn out (split)
// Bitmask: g_adjT[cw * N_TOK + r], bit j = adjacency[r][cw*32+j] != 0
__device__ unsigned g_adjT[(N_TOK / 32) * N_TOK];
// Split-K partials (max-free: only unnormalized O and l needed)
__device__ float g_po[NSPLIT][H_NUM * N_TOK * D_HEAD];
__device__ float g_pl[NSPLIT][H_NUM * N_TOK];

// ---------------------------------------------------------------------------
// MMA / ldmatrix / cp.async helpers
// ---------------------------------------------------------------------------
__device__ __forceinline__ u32 cvta_s(const void* p) {
    return (u32)__cvta_generic_to_shared(p);
}
__device__ __forceinline__ void ldsm_x4(u32* r, u32 a) {
    asm volatile("ldmatrix.sync.aligned.m8n8.x4.shared.b16 {%0,%1,%2,%3}, [%4];"
        : "=r"(r[0]), "=r"(r[1]), "=r"(r[2]), "=r"(r[3]) : "r"(a));
}
__device__ __forceinline__ void ldsm_x4t(u32* r, u32 a) {
    asm volatile("ldmatrix.sync.aligned.m8n8.x4.trans.shared.b16 {%0,%1,%2,%3}, [%4];"
        : "=r"(r[0]), "=r"(r[1]), "=r"(r[2]), "=r"(r[3]) : "r"(a));
}
__device__ __forceinline__ void mma_bf16(float* c, const u32* a, const u32* b) {
    asm volatile("mma.sync.aligned.m16n8k16.row.col.f32.bf16.bf16.f32 "
        "{%0,%1,%2,%3}, {%4,%5,%6,%7}, {%8,%9}, {%0,%1,%2,%3};"
        : "+f"(c[0]), "+f"(c[1]), "+f"(c[2]), "+f"(c[3])
        : "r"(a[0]), "r"(a[1]), "r"(a[2]), "r"(a[3]), "r"(b[0]), "r"(b[1]));
}
__device__ __forceinline__ void cpasync16(u32 dst, const void* src) {
    asm volatile("cp.async.ca.shared.global [%0], [%1], 16;" :: "r"(dst), "l"(src));
}
__device__ __forceinline__ void cp_commit() {
    asm volatile("cp.async.commit_group;");
}
template <int N>
__device__ __forceinline__ void cp_wait() {
    asm volatile("cp.async.wait_group %0;" :: "n"(N));
}
// pack2(f_low, f_high): bf16x2 reg, low half = first element
__device__ __forceinline__ u32 pack2(float flo, float fhi) {
    u32 d;
    asm("cvt.rn.bf16x2.f32 %0, %1, %2;" : "=r"(d) : "f"(fhi), "f"(flo));
    return d;
}
// Dekker split of a pair into hi bf16x2 + lo bf16x2 (residual)
__device__ __forceinline__ void split_pair(float f0, float f1, u32& hi, u32& lo) {
    u32 h = pack2(f0, f1);
    float h0 = __uint_as_float(h << 16);
    float h1 = __uint_as_float(h & 0xffff0000u);
    lo = pack2(f0 - h0, f1 - h1);
    hi = h;
}
// Spread 8 bits: bit i -> bit 4i
__device__ __forceinline__ unsigned spread8(unsigned x) {
    x = (x | (x << 12)) & 0x000F000Fu;
    x = (x | (x << 6))  & 0x03030303u;
    x = (x | (x << 3))  & 0x11111111u;
    return x;
}

// ---------------------------------------------------------------------------
// Kernel 0 (fused prep): blocks [0, SPLIT_BLKS) split fp32 inputs to bf16
// hi/lo (float4-wide); remaining blocks pack adjacency via int4 + ballot +
// bit-spread transpose (warp covers 128 columns of one row).
// ---------------------------------------------------------------------------
__global__ void prep_kernel(const float* __restrict__ x,
                            const float* __restrict__ Wq, const float* __restrict__ Wk,
                            const float* __restrict__ Wv, const float* __restrict__ Wo,
                            const int* __restrict__ adj) {
    const int tid = threadIdx.x;
    if (blockIdx.x < SPLIT_BLKS) {
        int i = blockIdx.x * 256 + tid;   // float4 index
        const float* src;
        __nv_bfloat16 *dh, *dl;
        int off;
        if (i < XQUADS) {
            src = x; dh = g_xh; dl = g_xl; off = i;
        } else {
            int j = i - XQUADS;           // 0 .. 4*WQUADS-1
            int w = j / WQUADS;           // weight matrix index 0..3 (FIXED)
            off = j - w * WQUADS;
            src = (w == 0) ? Wq : (w == 1) ? Wk : (w == 2) ? Wv : Wo;
            dh = g_wh[w]; dl = g_wl[w];
        }
        float4 v = ((const float4*)src)[off];
        u32 h0, l0, h1, l1;
        split_pair(v.x, v.y, h0, l0);
        split_pair(v.z, v.w, h1, l1);
        ((uint2*)dh)[off] = make_uint2(h0, h1);
        ((uint2*)dl)[off] = make_uint2(l0, l1);
    } else {
        int gw = (blockIdx.x - SPLIT_BLKS) * 8 + (tid >> 5);
        int lane = tid & 31;
        int r = gw >> 5;                  // row
        int g = gw & 31;                  // 128-column group
        const int4* a = (const int4*)(adj + (size_t)r * N_TOK + g * 128);
        int4 v = a[lane];                 // cols g*128 + 4*lane + {0..3}
        unsigned n = (v.x != 0 ? 1u : 0u) | (v.y != 0 ? 2u : 0u)
                   | (v.z != 0 ? 4u : 0u) | (v.w != 0 ? 8u : 0u);
        unsigned b0 = __ballot_sync(0xffffffffu, n & 1);
        unsigned b1 = __ballot_sync(0xffffffffu, n & 2);
        unsigned b2 = __ballot_sync(0xffffffffu, n & 4);
        unsigned b3 = __ballot_sync(0xffffffffu, n & 8);
        if (lane < 4) {
            // word w' = lane covers cols g*128 + 32*lane .. +31
            int sh = 8 * lane;
            unsigned w = spread8((b0 >> sh) & 0xFFu)
                       | (spread8((b1 >> sh) & 0xFFu) << 1)
                       | (spread8((b2 >> sh) & 0xFFu) << 2)
                       | (spread8((b3 >> sh) & 0xFFu) << 3);
            g_adjT[(size_t)(g * 4 + lane) * N_TOK + r] = w;
        }
    }
}

// ---------------------------------------------------------------------------
// Pipelined MMA GEMM: C[64x64] tile of A[4096,256] @ B[64,256]^T, 3-term bf16.
// 256 threads = 8 warps: warp wp -> rows (wp&3)*16, n-half (wp>>2)*32.
// 2-stage cp.async double buffer over 8 k-chunks of 32. Leaves c[4][4].
// ---------------------------------------------------------------------------
#define PSTAGE(Ah, Al, Bh, Bl, kc, st)                                          \
    {                                                                           \
        size_t ga = (size_t)(mt * 64 + srow) * E_DIM + (kc) * 32 + sdp * 8;     \
        size_t gb = (size_t)(nt * 64 + srow) * E_DIM + (kc) * 32 + sdp * 8;     \
        cpasync16(cvta_s(sAh[st]) + so, (Ah) + ga);                             \
        cpasync16(cvta_s(sAl[st]) + so, (Al) + ga);                             \
        cpasync16(cvta_s(sBh[st]) + so, (Bh) + gb);                             \
        cpasync16(cvta_s(sBl[st]) + so, (Bl) + gb);                             \
        cp_commit();                                                            \
    }

#define PROJ_PIPE(Ah, Al, Bh, Bl, mt, nt)                                       \
    __shared__ __align__(16) __nv_bfloat16 sAh[2][64 * SROW], sAl[2][64 * SROW];\
    __shared__ __align__(16) __nv_bfloat16 sBh[2][64 * SROW], sBl[2][64 * SROW];\
    const int tid = threadIdx.x;                                                \
    const int lane = tid & 31;                                                  \
    const int wp = tid >> 5;                                                    \
    float c[4][4];                                                              \
    _Pragma("unroll")                                                           \
    for (int ng = 0; ng < 4; ng++)                                              \
        c[ng][0] = c[ng][1] = c[ng][2] = c[ng][3] = 0.f;                        \
    const int srow = tid >> 2, sdp = tid & 3;                                   \
    const int so = srow * 80 + sdp * 16;                                        \
    PSTAGE(Ah, Al, Bh, Bl, 0, 0)                                                \
    for (int kc = 0; kc < 8; kc++) {                                            \
        const int cur = kc & 1, nxt = cur ^ 1;                                  \
        if (kc < 7) { PSTAGE(Ah, Al, Bh, Bl, kc + 1, nxt) cp_wait<1>(); }       \
        else cp_wait<0>();                                                      \
        __syncthreads();                                                        \
        _Pragma("unroll")                                                       \
        for (int ks = 0; ks < 2; ks++) {                                        \
            u32 ah[4], al[4];                                                   \
            u32 ao = ((wp & 3) * 16 + (lane & 15)) * 80 + ks * 32               \
                   + (lane >> 4) * 16;                                          \
            ldsm_x4(ah, cvta_s(sAh[cur]) + ao);                                 \
            ldsm_x4(al, cvta_s(sAl[cur]) + ao);                                 \
            _Pragma("unroll")                                                   \
            for (int np = 0; np < 2; np++) {                                    \
                u32 bh[4], bl[4];                                               \
                u32 bo_ = ((wp >> 2) * 32 + np * 16 + ((lane >> 4) & 1) * 8     \
                         + (lane & 7)) * 80 + ((lane >> 3) & 1) * 16 + ks * 32; \
                ldsm_x4(bh, cvta_s(sBh[cur]) + bo_);                            \
                ldsm_x4(bl, cvta_s(sBl[cur]) + bo_);                            \
                mma_bf16(c[2 * np], ah, bh);                                    \
                mma_bf16(c[2 * np], ah, bl);                                    \
                mma_bf16(c[2 * np], al, bh);                                    \
                mma_bf16(c[2 * np + 1], ah, bh + 2);                            \
                mma_bf16(c[2 * np + 1], ah, bl + 2);                            \
                mma_bf16(c[2 * np + 1], al, bh + 2);                            \
            }                                                                   \
        }                                                                       \
        __syncthreads();                                                        \
    }

// Q/K/V projections via MMA, grid (4, 64, 3): nt, mt, which.
__global__ void __launch_bounds__(256) proj_mma(const float* __restrict__ bq,
                                                const float* __restrict__ bk,
                                                const float* __restrict__ bv) {
    const int nt = blockIdx.x, mt = blockIdx.y, which = blockIdx.z;
    const float* bias = (which == 0) ? bq : (which == 1) ? bk : bv;
    const float scale = (which == 0)
        ? 0.17677669529663688f * 1.4426950408889634f   // 1/sqrt(32) * log2(e)
        : 1.0f;
    __nv_bfloat16* Ch = (which == 0) ? g_qh : (which == 1) ? g_kh : g_vh;
    __nv_bfloat16* Cl = (which == 0) ? g_ql : (which == 1) ? g_kl : g_vl;
    const __nv_bfloat16* Bh = g_wh[which];
    const __nv_bfloat16* Bl = g_wl[which];

    PROJ_PIPE(g_xh, g_xl, Bh, Bl, mt, nt)

    const int r0 = mt * 64 + (wp & 3) * 16 + (lane >> 2);
    const int r1 = r0 + 8;
#pragma unroll
    for (int ng = 0; ng < 4; ng++) {
        int col = nt * 64 + (wp >> 2) * 32 + ng * 8 + 2 * (lane & 3);
        float b0 = bias[col], b1 = bias[col + 1];
        float v0 = (c[ng][0] + b0) * scale;
        float v1 = (c[ng][1] + b1) * scale;
        float v2 = (c[ng][2] + b0) * scale;
        float v3 = (c[ng][3] + b1) * scale;
        u32 h, l;
        split_pair(v0, v1, h, l);
        *(u32*)(Ch + (size_t)r0 * E_DIM + col) = h;
        *(u32*)(Cl + (size_t)r0 * E_DIM + col) = l;
        split_pair(v2, v3, h, l);
        *(u32*)(Ch + (size_t)r1 * E_DIM + col) = h;
        *(u32*)(Cl + (size_t)r1 * E_DIM + col) = l;
    }
}

// Output projection via MMA, grid (4, 64). A = attention output (pre-split).
__global__ void __launch_bounds__(256) out_mma(const float* __restrict__ bo,
                                               float* __restrict__ out) {
    const int nt = blockIdx.x, mt = blockIdx.y;

    PROJ_PIPE(g_ah, g_al, g_wh[3], g_wl[3], mt, nt)

    const int r0 = mt * 64 + (wp & 3) * 16 + (lane >> 2);
    const int r1 = r0 + 8;
#pragma unroll
    for (int ng = 0; ng < 4; ng++) {
        int col = nt * 64 + (wp >> 2) * 32 + ng * 8 + 2 * (lane & 3);
        float b0 = bo[col], b1 = bo[col + 1];
        float2 s0 = make_float2(c[ng][0] + b0, c[ng][1] + b1);
        float2 s1 = make_float2(c[ng][2] + b0, c[ng][3] + b1);
        *(float2*)(out + (size_t)r0 * E_DIM + col) = s0;
        *(float2*)(out + (size_t)r1 * E_DIM + col) = s1;
    }
}

// ---------------------------------------------------------------------------
// Phase macros for the pipelined attention mainloop (round-15 champion)
// ---------------------------------------------------------------------------
#define S_PHASE(kaH_, kaL_)                                                     \
    _Pragma("unroll")                                                           \
    for (int np = 0; np < 4; np++) {                                            \
        s[2 * np][0] = s[2 * np][1] = s[2 * np][2] = s[2 * np][3] = 0.f;        \
        s[2 * np + 1][0] = s[2 * np + 1][1] = 0.f;                              \
        s[2 * np + 1][2] = s[2 * np + 1][3] = 0.f;                              \
        _Pragma("unroll")                                                       \
        for (int ks = 0; ks < 2; ks++) {                                        \
            u32 bh[4], bl[4];                                                   \
            u32 off = np * 1280 + ks * 32;                                      \
            ldsm_x4(bh, (kaH_) + off);                                          \
            ldsm_x4(bl, (kaL_) + off);                                          \
            mma_bf16(s[2 * np], qh[ks], bh);                                    \
            mma_bf16(s[2 * np], qh[ks], bl);                                    \
            mma_bf16(s[2 * np], ql[ks], bh);                                    \
            mma_bf16(s[2 * np + 1], qh[ks], bh + 2);                            \
            mma_bf16(s[2 * np + 1], qh[ks], bl + 2);                            \
            mma_bf16(s[2 * np + 1], ql[ks], bh + 2);                            \
        }                                                                       \
    }

#define EXP2_PACK(w00_, w01_, w10_, w11_)                                       \
    {                                                                           \
        const int sh2 = 2 * (lane & 3);                                         \
        _Pragma("unroll")                                                       \
        for (int ng = 0; ng < 8; ng++) {                                        \
            u32 wr0 = (ng < 4) ? (w00_) : (w01_);                               \
            u32 wr1 = (ng < 4) ? (w10_) : (w11_);                               \
            int sh = (ng & 3) * 8 + sh2;                                        \
            if (!((wr0 >> sh) & 1))       s[ng][0] = -INFINITY;                 \
            if (!((wr0 >> (sh + 1)) & 1)) s[ng][1] = -INFINITY;                 \
            if (!((wr1 >> sh) & 1))       s[ng][2] = -INFINITY;                 \
            if (!((wr1 >> (sh + 1)) & 1)) s[ng][3] = -INFINITY;                 \
        }                                                                       \
        _Pragma("unroll")                                                       \
        for (int ng = 0; ng < 8; ng++) {                                        \
            s[ng][0] = exp2f(s[ng][0]);                                         \
            s[ng][1] = exp2f(s[ng][1]);                                         \
            s[ng][2] = exp2f(s[ng][2]);                                         \
            s[ng][3] = exp2f(s[ng][3]);                                         \
            l0 += s[ng][0] + s[ng][1];                                          \
            l1 += s[ng][2] + s[ng][3];                                          \
        }                                                                       \
        _Pragma("unroll")                                                       \
        for (int ks = 0; ks < 4; ks++) {                                        \
            split_pair(s[2 * ks][0],     s[2 * ks][1],     paH[ks][0], paL[ks][0]); \
            split_pair(s[2 * ks][2],     s[2 * ks][3],     paH[ks][1], paL[ks][1]); \
            split_pair(s[2 * ks + 1][0], s[2 * ks + 1][1], paH[ks][2], paL[ks][2]); \
            split_pair(s[2 * ks + 1][2], s[2 * ks + 1][3], paH[ks][3], paL[ks][3]); \
        }                                                                       \
    }

#define PV_PHASE(vaH_, vaL_)                                                    \
    _Pragma("unroll")                                                           \
    for (int ks = 0; ks < 4; ks++) {                                            \
        _Pragma("unroll")                                                       \
        for (int np = 0; np < 2; np++) {                                        \
            u32 bh[4], bl[4];                                                   \
            u32 off = ks * 1280 + np * 32;                                      \
            ldsm_x4t(bh, (vaH_) + off);                                         \
            ldsm_x4t(bl, (vaL_) + off);                                         \
            mma_bf16(o[2 * np], paH[ks], bh);                                   \
            mma_bf16(o[2 * np], paH[ks], bl);                                   \
            mma_bf16(o[2 * np], paL[ks], bh);                                   \
            mma_bf16(o[2 * np + 1], paH[ks], bh + 2);                           \
            mma_bf16(o[2 * np + 1], paH[ks], bl + 2);                           \
            mma_bf16(o[2 * np + 1], paL[ks], bh + 2);                           \
        }                                                                       \
    }

#define STAGE_TILE(t, st)                                                       \
    {                                                                           \
        size_t g0 = (size_t)((t) * 64 + row0) * E_DIM + h * D_HEAD + dp0 * 8;   \
        size_t g1 = (size_t)((t) * 64 + row1) * E_DIM + h * D_HEAD + dp1 * 8;   \
        u32 kh = cvta_s(sKh[st]), kl = cvta_s(sKl[st]);                         \
        u32 vh = cvta_s(sVh[st]), vl = cvta_s(sVl[st]);                         \
        cpasync16(kh + so0, g_kh + g0); cpasync16(kh + so1, g_kh + g1);         \
        cpasync16(kl + so0, g_kl + g0); cpasync16(kl + so1, g_kl + g1);         \
        cpasync16(vh + so0, g_vh + g0); cpasync16(vh + so1, g_vh + g1);         \
        cpasync16(vl + so0, g_vl + g0); cpasync16(vl + so1, g_vl + g1);         \
        cp_commit();                                                            \
    }

// ---------------------------------------------------------------------------
// Kernel 3: split-K(x2) tensor-core masked flash attention, max-free exp2
// softmax, software-pipelined (PV(jj)+S(jj+1) one tensor burst). UNCHANGED
// from round 15. Grid (64, 8, 2), 128 threads.
// ---------------------------------------------------------------------------
__global__ void __launch_bounds__(128) attn_mma_kernel() {
    __shared__ __align__(16) __nv_bfloat16 sKh[2][64 * SROW], sKl[2][64 * SROW];
    __shared__ __align__(16) __nv_bfloat16 sVh[2][64 * SROW], sVl[2][64 * SROW];

    const int tid = threadIdx.x;
    const int lane = tid & 31;
    const int wp = tid >> 5;
    const int h = blockIdx.y;
    const int z = blockIdx.z;
    const int qb = blockIdx.x * 64;
    const int jt0 = z * TPS;

    const int row0 = tid >> 2, dp0 = tid & 3;
    const int row1 = (tid + 128) >> 2, dp1 = tid & 3;
    const int so0 = row0 * 80 + dp0 * 16;
    const int so1 = row1 * 80 + dp1 * 16;

    // ---- Stage Q tile (hi/lo) into stage-0 K buffers, build A-fragments ----
    {
        size_t gq0 = (size_t)(qb + row0) * E_DIM + h * D_HEAD + dp0 * 8;
        size_t gq1 = (size_t)(qb + row1) * E_DIM + h * D_HEAD + dp1 * 8;
        *(uint4*)((char*)sKh[0] + so0) = *(const uint4*)(g_qh + gq0);
        *(uint4*)((char*)sKh[0] + so1) = *(const uint4*)(g_qh + gq1);
        *(uint4*)((char*)sKl[0] + so0) = *(const uint4*)(g_ql + gq0);
        *(uint4*)((char*)sKl[0] + so1) = *(const uint4*)(g_ql + gq1);
    }
    __syncthreads();

    u32 qh[2][4], ql[2][4];
    {
        int arow = wp * 16 + (lane & 15);
        int acol = (lane >> 4) * 8;
        u32 bh = cvta_s(sKh[0]), bl = cvta_s(sKl[0]);
#pragma unroll
        for (int ks = 0; ks < 2; ks++) {
            u32 ao = arow * 80 + (ks * 16 + acol) * 2;
            ldsm_x4(qh[ks], bh + ao);
            ldsm_x4(ql[ks], bl + ao);
        }
    }
    __syncthreads();

    // ---- Prefetch tiles jt0 -> stage0 and jt0+1 -> stage1 (2 groups) ----
    STAGE_TILE(jt0, 0)
    STAGE_TILE(jt0 + 1, 1)

    float o[4][4];
#pragma unroll
    for (int nd = 0; nd < 4; nd++)
        o[nd][0] = o[nd][1] = o[nd][2] = o[nd][3] = 0.f;
    float l0 = 0.f, l1 = 0.f;
    float s[8][4];
    u32 paH[4][4], paL[4][4];

    const int r0 = qb + wp * 16 + (lane >> 2);
    const int r1 = r0 + 8;

    const u32 kofs4 = (((lane >> 4) & 1) * 8 + (lane & 7)) * 80
                    + ((lane >> 3) & 1) * 16;
    const u32 vofs4 = (lane & 15) * 80 + ((lane >> 4) & 1) * 16;
    const u32 kaH[2] = {cvta_s(sKh[0]) + kofs4, cvta_s(sKh[1]) + kofs4};
    const u32 kaL[2] = {cvta_s(sKl[0]) + kofs4, cvta_s(sKl[1]) + kofs4};
    const u32 vaH[2] = {cvta_s(sVh[0]) + vofs4, cvta_s(sVh[1]) + vofs4};
    const u32 vaL[2] = {cvta_s(sVl[0]) + vofs4, cvta_s(sVl[1]) + vofs4};

    // ---- Prologue: S(jt0) + exp2 -> P(jt0) ----
    {
        u32 w00 = g_adjT[(size_t)(jt0 * 2 + 0) * N_TOK + r0];
        u32 w01 = g_adjT[(size_t)(jt0 * 2 + 1) * N_TOK + r0];
        u32 w10 = g_adjT[(size_t)(jt0 * 2 + 0) * N_TOK + r1];
        u32 w11 = g_adjT[(size_t)(jt0 * 2 + 1) * N_TOK + r1];
        cp_wait<1>();
        __syncthreads();
        S_PHASE(kaH[0], kaL[0])
        EXP2_PACK(w00, w01, w10, w11)
    }

    // ---- Pipelined mainloop: iteration jj does PV(jj) and S(jj+1) ----
    for (int jj = 0; jj < TPS - 1; jj++) {
        const int jt = jt0 + jj;
        const int cur = jj & 1, nxt = cur ^ 1;

        cp_wait<0>();
        __syncthreads();

        u32 w00 = g_adjT[(size_t)((jt + 1) * 2 + 0) * N_TOK + r0];
        u32 w01 = g_adjT[(size_t)((jt + 1) * 2 + 1) * N_TOK + r0];
        u32 w10 = g_adjT[(size_t)((jt + 1) * 2 + 0) * N_TOK + r1];
        u32 w11 = g_adjT[(size_t)((jt + 1) * 2 + 1) * N_TOK + r1];

        PV_PHASE(vaH[cur], vaL[cur])
        S_PHASE(kaH[nxt], kaL[nxt])

        __syncthreads();
        if (jj + 2 < TPS) STAGE_TILE(jt + 2, cur)

        EXP2_PACK(w00, w01, w10, w11)
    }

    // ---- Epilogue: PV(last tile) ----
    PV_PHASE(vaH[(TPS - 1) & 1], vaL[(TPS - 1) & 1])

    // ---- write unnormalized partials ----
    l0 += __shfl_xor_sync(0xffffffffu, l0, 1);
    l0 += __shfl_xor_sync(0xffffffffu, l0, 2);
    l1 += __shfl_xor_sync(0xffffffffu, l1, 1);
    l1 += __shfl_xor_sync(0xffffffffu, l1, 2);
    const int idx0 = h * N_TOK + r0;
    const int idx1 = h * N_TOK + r1;
    if ((lane & 3) == 0) {
        g_pl[z][idx0] = l0;
        g_pl[z][idx1] = l1;
    }
    float* p0 = &g_po[z][(size_t)idx0 * D_HEAD];
    float* p1 = &g_po[z][(size_t)idx1 * D_HEAD];
#pragma unroll
    for (int nd = 0; nd < 4; nd++) {
        int cn = nd * 8 + 2 * (lane & 3);
        *(float2*)(p0 + cn) = make_float2(o[nd][0], o[nd][1]);
        *(float2*)(p1 + cn) = make_float2(o[nd][2], o[nd][3]);
    }
}

// ---------------------------------------------------------------------------
// Kernel 4: combine the split partials, normalize, write hi/lo bf16 split.
// ---------------------------------------------------------------------------
__global__ void combine_kernel() {
    int c = blockIdx.x * 256 + threadIdx.x;
    int cc = c & 7;
    int idx = c >> 3;                 // h*N + r
    float lsum = 0.f;
#pragma unroll
    for (int s = 0; s < NSPLIT; s++) lsum += g_pl[s][idx];
    float inv = 1.f / lsum;
    float v0 = 0.f, v1 = 0.f, v2 = 0.f, v3 = 0.f;
#pragma unroll
    for (int s = 0; s < NSPLIT; s++) {
        float4 a = *(const float4*)&g_po[s][(size_t)idx * D_HEAD + cc * 4];
        v0 += a.x; v1 += a.y; v2 += a.z; v3 += a.w;
    }
    v0 *= inv; v1 *= inv; v2 *= inv; v3 *= inv;
    int r = idx & (N_TOK - 1);
    int h = idx >> 12;
    size_t off = (size_t)r * E_DIM + h * D_HEAD + cc * 4;
    u32 hh, ll;
    split_pair(v0, v1, hh, ll);
    *(u32*)(g_ah + off) = hh;
    *(u32*)(g_al + off) = ll;
    split_pair(v2, v3, hh, ll);
    *(u32*)(g_ah + off + 2) = hh;
    *(u32*)(g_al + off + 2) = ll;
}

// ---------------------------------------------------------------------------
extern "C" void kernel_launch(void* const* d_in, const int* in_sizes, int n_in,
                              void* d_out, int out_size) {
    const float* x   = (const float*)d_in[0];
    const int*   adj = (const int*)d_in[1];
    const float* Wq  = (const float*)d_in[2];
    const float* bq  = (const float*)d_in[3];
    const float* Wk  = (const float*)d_in[4];
    const float* bk  = (const float*)d_in[5];
    const float* Wv  = (const float*)d_in[6];
    const float* bv  = (const float*)d_in[7];
    const float* Wo  = (const float*)d_in[8];
    const float* bo  = (const float*)d_in[9];
    float* out = (float*)d_out;

    prep_kernel<<<SPLIT_BLKS + PACK_BLKS, 256>>>(x, Wq, Wk, Wv, Wo, adj);

    proj_mma<<<dim3(4, 64, 3), 256>>>(bq, bk, bv);

    attn_mma_kernel<<<dim3(N_TOK / 64, H_NUM, NSPLIT), 128>>>();

    combine_kernel<<<(H_NUM * N_TOK * 8) / 256, 256>>>();

    out_mma<<<dim3(4, 64), 256>>>(bo, out);
}